// round 1
// baseline (speedup 1.0000x reference)
#include <cuda_runtime.h>
#include <cstdint>
#include <cstddef>

// ---------------------------------------------------------------------------
// TokenPacker: 9 GEMMs (E=K=1024) + 3 LN + GELU epilogues + 1x4 attention
// Precision strategy: 3xTF32 (hi/lo split) on mma.sync.m16n8k8 -> ~fp32 accuracy
// ---------------------------------------------------------------------------

#define E_DIM 1024
#define NQ 144
#define TN 576
#define NB 64
#define M_BIG  (NB * TN)   // 36864
#define M_SML  (NB * NQ)   // 9216

// scratch (device globals; no allocation allowed)
__device__ float g_tmp[(size_t)M_BIG * E_DIM];
__device__ float g_key[(size_t)M_BIG * E_DIM];
__device__ float g_val[(size_t)M_BIG * E_DIM];
__device__ float g_kh [(size_t)M_BIG * E_DIM];
__device__ float g_vh [(size_t)M_BIG * E_DIM];
__device__ float g_qry[(size_t)M_SML * E_DIM];
__device__ float g_qh [(size_t)M_SML * E_DIM];
__device__ float g_att[(size_t)M_SML * E_DIM];

// ---------------------------------------------------------------------------
// helpers
// ---------------------------------------------------------------------------
__device__ __forceinline__ uint32_t f2tf32(float x) {
    uint32_t r;
    asm("cvt.rna.tf32.f32 %0, %1;" : "=r"(r) : "f"(x));
    return r;
}

__device__ __forceinline__ void mma8(float* c, const uint32_t* a, const uint32_t* b) {
    asm volatile(
        "mma.sync.aligned.m16n8k8.row.col.f32.tf32.tf32.f32 "
        "{%0,%1,%2,%3}, {%4,%5,%6,%7}, {%8,%9}, {%0,%1,%2,%3};\n"
        : "+f"(c[0]), "+f"(c[1]), "+f"(c[2]), "+f"(c[3])
        : "r"(a[0]), "r"(a[1]), "r"(a[2]), "r"(a[3]), "r"(b[0]), "r"(b[1]));
}

__device__ __forceinline__ void cp_async16(void* smem, const void* gmem) {
    uint32_t s = (uint32_t)__cvta_generic_to_shared(smem);
    asm volatile("cp.async.ca.shared.global [%0], [%1], 16;\n" :: "r"(s), "l"(gmem));
}
__device__ __forceinline__ void cp_commit() { asm volatile("cp.async.commit_group;\n"); }
template <int N>
__device__ __forceinline__ void cp_wait() { asm volatile("cp.async.wait_group %0;\n" :: "n"(N)); }

// ---------------------------------------------------------------------------
// GEMM: C[M,1024] = A[M,1024] @ B^T (B row-major [1024,1024], K contiguous)
// epi: 0 = none, 1 = +bias, 2 = gelu(+bias)
// BM=128, BN=128, BK=16, 256 threads, 8 warps (4x2), warp tile 32x64
// ---------------------------------------------------------------------------
#define BM 128
#define BN 128
#define BK 16
#define ROWLEN 20   // BK + 4 pad (floats)

__global__ __launch_bounds__(256)
void gemm_tf32x3(const float* __restrict__ A, const float* __restrict__ B,
                 const float* __restrict__ bias, float* __restrict__ C, int epi)
{
    __shared__ float As[2][BM * ROWLEN];
    __shared__ float Bs[2][BN * ROWLEN];

    const int tid  = threadIdx.x;
    const int lane = tid & 31;
    const int wid  = tid >> 5;
    const int wm   = (wid >> 1) * 32;   // warp M offset in tile
    const int wn   = (wid & 1) * 64;    // warp N offset in tile
    const int bm   = blockIdx.y;
    const int bn   = blockIdx.x;
    const int K    = E_DIM;

    float acc[2][8][4];
    #pragma unroll
    for (int mt = 0; mt < 2; mt++)
        #pragma unroll
        for (int nt = 0; nt < 8; nt++)
            #pragma unroll
            for (int i = 0; i < 4; i++) acc[mt][nt][i] = 0.0f;

    // tile loaders: 128 rows x 16 cols = 512 float4 per matrix, 2 per thread
    const int lrow = tid >> 2;        // 0..63
    const int lcv  = (tid & 3) * 4;   // 0,4,8,12

    auto load_tiles = [&](int kt, int buf) {
        const int k0 = kt * BK;
        #pragma unroll
        for (int r = 0; r < 2; r++) {
            int row = lrow + r * 64;
            cp_async16(&As[buf][row * ROWLEN + lcv],
                       A + (size_t)(bm * BM + row) * K + k0 + lcv);
        }
        #pragma unroll
        for (int r = 0; r < 2; r++) {
            int row = lrow + r * 64;
            cp_async16(&Bs[buf][row * ROWLEN + lcv],
                       B + (size_t)(bn * BN + row) * K + k0 + lcv);
        }
    };

    load_tiles(0, 0);
    cp_commit();

    const int NKT = K / BK;  // 64
    for (int kt = 0; kt < NKT; kt++) {
        const int buf = kt & 1;
        if (kt + 1 < NKT) {
            load_tiles(kt + 1, buf ^ 1);
            cp_commit();
            cp_wait<1>();
        } else {
            cp_wait<0>();
        }
        __syncthreads();

        #pragma unroll
        for (int ks = 0; ks < 2; ks++) {
            const int kb = ks * 8;
            uint32_t ah[2][4], al[2][4];
            #pragma unroll
            for (int mt = 0; mt < 2; mt++)
                #pragma unroll
                for (int i = 0; i < 4; i++) {
                    int row = wm + mt * 16 + (lane >> 2) + (i & 1) * 8;
                    int col = kb + (lane & 3) + (i >> 1) * 4;
                    float v = As[buf][row * ROWLEN + col];
                    uint32_t hi = f2tf32(v);
                    ah[mt][i] = hi;
                    al[mt][i] = f2tf32(v - __uint_as_float(hi));
                }
            uint32_t bh[8][2], bl[8][2];
            #pragma unroll
            for (int nt = 0; nt < 8; nt++)
                #pragma unroll
                for (int j = 0; j < 2; j++) {
                    int nrow = wn + nt * 8 + (lane >> 2);
                    int col  = kb + (lane & 3) + j * 4;
                    float v = Bs[buf][nrow * ROWLEN + col];
                    uint32_t hi = f2tf32(v);
                    bh[nt][j] = hi;
                    bl[nt][j] = f2tf32(v - __uint_as_float(hi));
                }
            #pragma unroll
            for (int mt = 0; mt < 2; mt++)
                #pragma unroll
                for (int nt = 0; nt < 8; nt++) {
                    mma8(acc[mt][nt], ah[mt], bh[nt]);
                    mma8(acc[mt][nt], al[mt], bh[nt]);
                    mma8(acc[mt][nt], ah[mt], bl[nt]);
                }
        }
        __syncthreads();
    }

    // epilogue
    #pragma unroll
    for (int mt = 0; mt < 2; mt++) {
        #pragma unroll
        for (int nt = 0; nt < 8; nt++) {
            int row0 = bm * BM + wm + mt * 16 + (lane >> 2);
            int col  = bn * BN + wn + nt * 8 + (lane & 3) * 2;
            float bv0 = 0.0f, bv1 = 0.0f;
            if (epi != 0) { bv0 = bias[col]; bv1 = bias[col + 1]; }
            float c0 = acc[mt][nt][0] + bv0;
            float c1 = acc[mt][nt][1] + bv1;
            float c2 = acc[mt][nt][2] + bv0;
            float c3 = acc[mt][nt][3] + bv1;
            if (epi == 2) {
                c0 = 0.5f * c0 * (1.0f + erff(c0 * 0.7071067811865476f));
                c1 = 0.5f * c1 * (1.0f + erff(c1 * 0.7071067811865476f));
                c2 = 0.5f * c2 * (1.0f + erff(c2 * 0.7071067811865476f));
                c3 = 0.5f * c3 * (1.0f + erff(c3 * 0.7071067811865476f));
            }
            *(float2*)(C + (size_t)row0 * E_DIM + col)       = make_float2(c0, c1);
            *(float2*)(C + (size_t)(row0 + 8) * E_DIM + col) = make_float2(c2, c3);
        }
    }
}

// ---------------------------------------------------------------------------
// LayerNorm over last dim (1024), in-place. One block (256 thr) per row.
// ---------------------------------------------------------------------------
__global__ __launch_bounds__(256)
void ln_kernel(float* __restrict__ X, const float* __restrict__ w, const float* __restrict__ b)
{
    const size_t row = blockIdx.x;
    float4* xp = (float4*)(X + row * E_DIM);
    const int tid  = threadIdx.x;
    const int lane = tid & 31;
    const int wid  = tid >> 5;

    float4 v = xp[tid];
    float s  = v.x + v.y + v.z + v.w;
    float ss = v.x * v.x + v.y * v.y + v.z * v.z + v.w * v.w;
    #pragma unroll
    for (int off = 16; off; off >>= 1) {
        s  += __shfl_xor_sync(0xffffffffu, s, off);
        ss += __shfl_xor_sync(0xffffffffu, ss, off);
    }
    __shared__ float rs[8], rss[8];
    if (lane == 0) { rs[wid] = s; rss[wid] = ss; }
    __syncthreads();
    float ts = 0.0f, tss = 0.0f;
    #pragma unroll
    for (int i = 0; i < 8; i++) { ts += rs[i]; tss += rss[i]; }
    const float mean = ts * (1.0f / 1024.0f);
    const float var  = tss * (1.0f / 1024.0f) - mean * mean;
    const float inv  = rsqrtf(var + 1e-6f);

    const float4 w4 = ((const float4*)w)[tid];
    const float4 b4 = ((const float4*)b)[tid];
    v.x = (v.x - mean) * inv * w4.x + b4.x;
    v.y = (v.y - mean) * inv * w4.y + b4.y;
    v.z = (v.z - mean) * inv * w4.z + b4.z;
    v.w = (v.w - mean) * inv * w4.w + b4.w;
    xp[tid] = v;
}

// ---------------------------------------------------------------------------
// Attention: per (n, q): 8 heads x (1 query, 4 keys) softmax attention.
// Key/value token for (q, kk): t = (2*qr + kk/2)*24 + 2*qc + kk%2
// Block = 256 thr (8 warps = 8 heads), grid = N*NQ.
// ---------------------------------------------------------------------------
__global__ __launch_bounds__(256)
void attn_kernel(const float* __restrict__ qh, const float* __restrict__ kh,
                 const float* __restrict__ vh, float* __restrict__ out)
{
    const int bq   = blockIdx.x;       // n*NQ + q
    const int n    = bq / NQ;
    const int q    = bq - n * NQ;
    const int h    = threadIdx.x >> 5;
    const int lane = threadIdx.x & 31;
    const int qr   = q / 12;
    const int qc   = q - qr * 12;

    const size_t qoff = (size_t)bq * E_DIM + h * 128 + lane * 4;
    const float4 qv = *(const float4*)(qh + qoff);

    float s[4];
    float4 vv[4];
    #pragma unroll
    for (int kk = 0; kk < 4; kk++) {
        const int t = (qr * 2 + (kk >> 1)) * 24 + qc * 2 + (kk & 1);
        const size_t krow = (size_t)(n * TN + t) * E_DIM + h * 128 + lane * 4;
        const float4 k4 = *(const float4*)(kh + krow);
        vv[kk] = *(const float4*)(vh + krow);
        float d = qv.x * k4.x + qv.y * k4.y + qv.z * k4.z + qv.w * k4.w;
        #pragma unroll
        for (int off = 16; off; off >>= 1) d += __shfl_xor_sync(0xffffffffu, d, off);
        s[kk] = d * 0.08838834764831845f;   // 1/sqrt(128)
    }
    const float m = fmaxf(fmaxf(s[0], s[1]), fmaxf(s[2], s[3]));
    float p[4], sum = 0.0f;
    #pragma unroll
    for (int kk = 0; kk < 4; kk++) { p[kk] = expf(s[kk] - m); sum += p[kk]; }
    const float inv = 1.0f / sum;
    float4 o = make_float4(0.f, 0.f, 0.f, 0.f);
    #pragma unroll
    for (int kk = 0; kk < 4; kk++) {
        const float pk = p[kk] * inv;
        o.x += pk * vv[kk].x; o.y += pk * vv[kk].y;
        o.z += pk * vv[kk].z; o.w += pk * vv[kk].w;
    }
    *(float4*)(out + qoff) = o;
}

// ---------------------------------------------------------------------------
// launch
// ---------------------------------------------------------------------------
extern "C" void kernel_launch(void* const* d_in, const int* in_sizes, int n_in,
                              void* d_out, int out_size)
{
    const float* x      = (const float*)d_in[0];
    const float* x_feat = (const float*)d_in[1];
    const float* w_q    = (const float*)d_in[2];
    const float* w_k1   = (const float*)d_in[3];
    const float* b_k1   = (const float*)d_in[4];
    const float* w_k2   = (const float*)d_in[5];
    const float* b_k2   = (const float*)d_in[6];
    const float* w_v1   = (const float*)d_in[7];
    const float* b_v1   = (const float*)d_in[8];
    const float* w_v2   = (const float*)d_in[9];
    const float* b_v2   = (const float*)d_in[10];
    const float* ln_q_w = (const float*)d_in[11];
    const float* ln_q_b = (const float*)d_in[12];
    const float* ln_k_w = (const float*)d_in[13];
    const float* ln_k_b = (const float*)d_in[14];
    const float* ln_v_w = (const float*)d_in[15];
    const float* ln_v_b = (const float*)d_in[16];
    const float* in_w   = (const float*)d_in[17];
    const float* in_b   = (const float*)d_in[18];
    const float* out_w  = (const float*)d_in[19];
    const float* out_b  = (const float*)d_in[20];
    float* out = (float*)d_out;

    float *tmp, *key, *val, *kh, *vh, *qry, *qh, *att;
    cudaGetSymbolAddress((void**)&tmp, g_tmp);
    cudaGetSymbolAddress((void**)&key, g_key);
    cudaGetSymbolAddress((void**)&val, g_val);
    cudaGetSymbolAddress((void**)&kh,  g_kh);
    cudaGetSymbolAddress((void**)&vh,  g_vh);
    cudaGetSymbolAddress((void**)&qry, g_qry);
    cudaGetSymbolAddress((void**)&qh,  g_qh);
    cudaGetSymbolAddress((void**)&att, g_att);

    dim3 gridBig(E_DIM / BN, M_BIG / BM);   // (8, 288)
    dim3 gridSml(E_DIM / BN, M_SML / BM);   // (8, 72)
    dim3 blk(256);

    // key path
    gemm_tf32x3<<<gridBig, blk>>>(x_feat, w_k1, b_k1, tmp, 2);  // gelu
    gemm_tf32x3<<<gridBig, blk>>>(tmp, w_k2, b_k2, key, 1);
    ln_kernel<<<M_BIG, blk>>>(key, ln_k_w, ln_k_b);
    // value path
    gemm_tf32x3<<<gridBig, blk>>>(x_feat, w_v1, b_v1, tmp, 2);  // gelu
    gemm_tf32x3<<<gridBig, blk>>>(tmp, w_v2, b_v2, val, 1);
    ln_kernel<<<M_BIG, blk>>>(val, ln_v_w, ln_v_b);
    // query path
    gemm_tf32x3<<<gridSml, blk>>>(x, w_q, nullptr, qry, 0);
    ln_kernel<<<M_SML, blk>>>(qry, ln_q_w, ln_q_b);
    // in-proj (q/k/v heads)
    gemm_tf32x3<<<gridSml, blk>>>(qry, in_w,                     in_b,        qh, 1);
    gemm_tf32x3<<<gridBig, blk>>>(key, in_w + (size_t)E_DIM * E_DIM,     in_b + E_DIM,     kh, 1);
    gemm_tf32x3<<<gridBig, blk>>>(val, in_w + (size_t)2 * E_DIM * E_DIM, in_b + 2 * E_DIM, vh, 1);
    // attention
    attn_kernel<<<M_SML, blk>>>(qh, kh, vh, att);
    // out-proj -> d_out
    gemm_tf32x3<<<gridSml, blk>>>(att, out_w, out_b, out, 1);
}

// round 2
// speedup vs baseline: 1.8580x; 1.8580x over previous
#include <cuda_runtime.h>
#include <cuda_fp16.h>
#include <cstdint>
#include <cstddef>

// ---------------------------------------------------------------------------
// TokenPacker, round 2: fp16x2 split GEMMs (m16n8k16, 3 mma terms), splits
// hoisted out of GEMM into producers (split kernel / GELU epi / LN epi / attn).
// ---------------------------------------------------------------------------

#define E_DIM 1024
#define NQ 144
#define TN 576
#define NB 64
#define M_BIG  (NB * TN)   // 36864
#define M_SML  (NB * NQ)   // 9216

#define WSLOT ((size_t)E_DIM * E_DIM)  // 1M elements per weight slot

// fp16 hi/lo activation planes
__device__ __half g_xf_h [(size_t)M_BIG * E_DIM];
__device__ __half g_xf_l [(size_t)M_BIG * E_DIM];
__device__ __half g_x_h  [(size_t)M_SML * E_DIM];
__device__ __half g_x_l  [(size_t)M_SML * E_DIM];
__device__ __half g_tmp_h[(size_t)M_BIG * E_DIM];
__device__ __half g_tmp_l[(size_t)M_BIG * E_DIM];
__device__ __half g_kn_h [(size_t)M_BIG * E_DIM];
__device__ __half g_kn_l [(size_t)M_BIG * E_DIM];
__device__ __half g_vn_h [(size_t)M_BIG * E_DIM];
__device__ __half g_vn_l [(size_t)M_BIG * E_DIM];
__device__ __half g_qn_h [(size_t)M_SML * E_DIM];
__device__ __half g_qn_l [(size_t)M_SML * E_DIM];
__device__ __half g_at_h [(size_t)M_SML * E_DIM];
__device__ __half g_at_l [(size_t)M_SML * E_DIM];
// fp16 weight slots: 0=wq 1=wk1 2=wk2 3=wv1 4=wv2 5,6,7=in_w 8=out_w
__device__ __half g_w_h[9 * WSLOT];
__device__ __half g_w_l[9 * WSLOT];
// fp32 scratch
__device__ float g_key[(size_t)M_BIG * E_DIM];
__device__ float g_val[(size_t)M_BIG * E_DIM];
__device__ float g_qry[(size_t)M_SML * E_DIM];
__device__ float g_qh [(size_t)M_SML * E_DIM];
__device__ float g_kh [(size_t)M_BIG * E_DIM];
__device__ float g_vh [(size_t)M_BIG * E_DIM];

// ---------------------------------------------------------------------------
// helpers
// ---------------------------------------------------------------------------
__device__ __forceinline__ void mma16(float* c, const uint32_t* a, const uint32_t* b) {
    asm volatile(
        "mma.sync.aligned.m16n8k16.row.col.f32.f16.f16.f32 "
        "{%0,%1,%2,%3}, {%4,%5,%6,%7}, {%8,%9}, {%0,%1,%2,%3};\n"
        : "+f"(c[0]), "+f"(c[1]), "+f"(c[2]), "+f"(c[3])
        : "r"(a[0]), "r"(a[1]), "r"(a[2]), "r"(a[3]), "r"(b[0]), "r"(b[1]));
}

__device__ __forceinline__ void cp_async16(void* smem, const void* gmem) {
    uint32_t s = (uint32_t)__cvta_generic_to_shared(smem);
    asm volatile("cp.async.ca.shared.global [%0], [%1], 16;\n" :: "r"(s), "l"(gmem));
}
__device__ __forceinline__ void cp_commit() { asm volatile("cp.async.commit_group;\n"); }
template <int N>
__device__ __forceinline__ void cp_wait() { asm volatile("cp.async.wait_group %0;\n" :: "n"(N)); }

__device__ __forceinline__ void split_store2(__half* __restrict__ hi, __half* __restrict__ lo,
                                             size_t off, float a, float b) {
    __half h0 = __float2half_rn(a), h1 = __float2half_rn(b);
    __half l0 = __float2half_rn(a - __half2float(h0));
    __half l1 = __float2half_rn(b - __half2float(h1));
    *(__half2*)(hi + off) = __halves2half2(h0, h1);
    *(__half2*)(lo + off) = __halves2half2(l0, l1);
}

__device__ __forceinline__ float gelu_exact(float x) {
    return 0.5f * x * (1.0f + erff(x * 0.7071067811865476f));
}

// ---------------------------------------------------------------------------
// split kernel: fp32 -> fp16 hi/lo planes
// ---------------------------------------------------------------------------
__global__ __launch_bounds__(256)
void split_f32(const float4* __restrict__ src, __half* __restrict__ hi,
               __half* __restrict__ lo, int n4)
{
    int i = blockIdx.x * blockDim.x + threadIdx.x;
    if (i < n4) {
        float4 v = src[i];
        size_t off = (size_t)i * 4;
        split_store2(hi, lo, off,     v.x, v.y);
        split_store2(hi, lo, off + 2, v.z, v.w);
    }
}

// ---------------------------------------------------------------------------
// GEMM: C[M,1024] = A[M,1024] @ B^T, A/B given as fp16 hi/lo planes.
// MODE 0: fp32 out, no bias.  MODE 1: fp32 out + bias.  MODE 2: gelu(+bias) -> hi/lo.
// BM=BN=128, BK=32, 256 thr, 8 warps (4x2), warp tile 32x64, cp.async dbl-buf.
// ---------------------------------------------------------------------------
#define BK 32
#define S16 40                 // halves per smem row (32 + 8 pad)
#define TILEH (128 * S16)      // halves per tile plane
#define GEMM_SMEM (2 * 4 * TILEH * 2)   // bytes = 81920

template<int MODE>
__global__ __launch_bounds__(256, 2)
void gemm_f16x2(const __half* __restrict__ Ah, const __half* __restrict__ Al,
                const __half* __restrict__ Bh, const __half* __restrict__ Bl,
                const float* __restrict__ bias,
                float* __restrict__ Cf,
                __half* __restrict__ Chi, __half* __restrict__ Clo)
{
    extern __shared__ __half sm[];
    const int tid  = threadIdx.x;
    const int lane = tid & 31;
    const int wid  = tid >> 5;
    const int wm   = (wid >> 1) * 32;
    const int wn   = (wid & 1) * 64;
    const int bm   = blockIdx.y;
    const int bn   = blockIdx.x;

    float acc[2][8][4];
    #pragma unroll
    for (int mt = 0; mt < 2; mt++)
        #pragma unroll
        for (int nt = 0; nt < 8; nt++)
            #pragma unroll
            for (int i = 0; i < 4; i++) acc[mt][nt][i] = 0.0f;

    auto load_tiles = [&](int kt, int buf) {
        const int k0 = kt * BK;
        __half* base = sm + buf * 4 * TILEH;
        #pragma unroll
        for (int t = 0; t < 2; t++) {
            int idx = tid + t * 256;          // 0..511
            int row = idx >> 2, c = idx & 3;  // c: 16B chunk (8 halves)
            size_t ga = (size_t)(bm * 128 + row) * E_DIM + k0 + c * 8;
            size_t gb = (size_t)(bn * 128 + row) * E_DIM + k0 + c * 8;
            uint32_t d = row * S16 + c * 8;
            cp_async16(base + d,             Ah + ga);
            cp_async16(base + TILEH + d,     Al + ga);
            cp_async16(base + 2 * TILEH + d, Bh + gb);
            cp_async16(base + 3 * TILEH + d, Bl + gb);
        }
    };

    load_tiles(0, 0);
    cp_commit();

    const int NKT = E_DIM / BK;  // 32
    for (int kt = 0; kt < NKT; kt++) {
        const int buf = kt & 1;
        if (kt + 1 < NKT) {
            load_tiles(kt + 1, buf ^ 1);
            cp_commit();
            cp_wait<1>();
        } else {
            cp_wait<0>();
        }
        __syncthreads();

        const __half* sAh = sm + buf * 4 * TILEH;
        const __half* sAl = sAh + TILEH;
        const __half* sBh = sAh + 2 * TILEH;
        const __half* sBl = sAh + 3 * TILEH;

        #pragma unroll
        for (int ks = 0; ks < 2; ks++) {
            const int kb = ks * 16;
            uint32_t ah[2][4], al[2][4];
            #pragma unroll
            for (int mt = 0; mt < 2; mt++)
                #pragma unroll
                for (int i = 0; i < 4; i++) {
                    int row = wm + mt * 16 + (lane >> 2) + ((i & 1) << 3);
                    int col = kb + ((lane & 3) << 1) + ((i >> 1) << 3);
                    ah[mt][i] = *(const uint32_t*)(sAh + row * S16 + col);
                    al[mt][i] = *(const uint32_t*)(sAl + row * S16 + col);
                }
            #pragma unroll
            for (int nt = 0; nt < 8; nt++) {
                int n = wn + nt * 8 + (lane >> 2);
                int k = kb + ((lane & 3) << 1);
                uint32_t bh[2], bl[2];
                bh[0] = *(const uint32_t*)(sBh + n * S16 + k);
                bh[1] = *(const uint32_t*)(sBh + n * S16 + k + 8);
                bl[0] = *(const uint32_t*)(sBl + n * S16 + k);
                bl[1] = *(const uint32_t*)(sBl + n * S16 + k + 8);
                #pragma unroll
                for (int mt = 0; mt < 2; mt++) {
                    mma16(acc[mt][nt], ah[mt], bh);
                    mma16(acc[mt][nt], al[mt], bh);
                    mma16(acc[mt][nt], ah[mt], bl);
                }
            }
        }
        __syncthreads();
    }

    // epilogue
    #pragma unroll
    for (int mt = 0; mt < 2; mt++) {
        #pragma unroll
        for (int nt = 0; nt < 8; nt++) {
            int row0 = bm * 128 + wm + mt * 16 + (lane >> 2);
            int col  = bn * 128 + wn + nt * 8 + ((lane & 3) << 1);
            float bv0 = 0.0f, bv1 = 0.0f;
            if (MODE != 0) { bv0 = bias[col]; bv1 = bias[col + 1]; }
            float c0 = acc[mt][nt][0] + bv0;
            float c1 = acc[mt][nt][1] + bv1;
            float c2 = acc[mt][nt][2] + bv0;
            float c3 = acc[mt][nt][3] + bv1;
            if (MODE == 2) {
                c0 = gelu_exact(c0); c1 = gelu_exact(c1);
                c2 = gelu_exact(c2); c3 = gelu_exact(c3);
                size_t o0 = (size_t)row0 * E_DIM + col;
                size_t o1 = (size_t)(row0 + 8) * E_DIM + col;
                split_store2(Chi, Clo, o0, c0, c1);
                split_store2(Chi, Clo, o1, c2, c3);
            } else {
                *(float2*)(Cf + (size_t)row0 * E_DIM + col)       = make_float2(c0, c1);
                *(float2*)(Cf + (size_t)(row0 + 8) * E_DIM + col) = make_float2(c2, c3);
            }
        }
    }
}

// ---------------------------------------------------------------------------
// LayerNorm over last dim (1024) -> fp16 hi/lo planes. 256 thr per row.
// ---------------------------------------------------------------------------
__global__ __launch_bounds__(256)
void ln_split(const float* __restrict__ X, __half* __restrict__ Hi, __half* __restrict__ Lo,
              const float* __restrict__ w, const float* __restrict__ b)
{
    const size_t row = blockIdx.x;
    const float4* xp = (const float4*)(X + row * E_DIM);
    const int tid  = threadIdx.x;
    const int lane = tid & 31;
    const int wid  = tid >> 5;

    float4 v = xp[tid];
    float s  = v.x + v.y + v.z + v.w;
    float ss = v.x * v.x + v.y * v.y + v.z * v.z + v.w * v.w;
    #pragma unroll
    for (int off = 16; off; off >>= 1) {
        s  += __shfl_xor_sync(0xffffffffu, s, off);
        ss += __shfl_xor_sync(0xffffffffu, ss, off);
    }
    __shared__ float rs[8], rss[8];
    if (lane == 0) { rs[wid] = s; rss[wid] = ss; }
    __syncthreads();
    float ts = 0.0f, tss = 0.0f;
    #pragma unroll
    for (int i = 0; i < 8; i++) { ts += rs[i]; tss += rss[i]; }
    const float mean = ts * (1.0f / 1024.0f);
    const float var  = tss * (1.0f / 1024.0f) - mean * mean;
    const float inv  = rsqrtf(var + 1e-6f);

    const float4 w4 = ((const float4*)w)[tid];
    const float4 b4 = ((const float4*)b)[tid];
    float y0 = (v.x - mean) * inv * w4.x + b4.x;
    float y1 = (v.y - mean) * inv * w4.y + b4.y;
    float y2 = (v.z - mean) * inv * w4.z + b4.z;
    float y3 = (v.w - mean) * inv * w4.w + b4.w;
    size_t off = row * E_DIM + (size_t)tid * 4;
    split_store2(Hi, Lo, off,     y0, y1);
    split_store2(Hi, Lo, off + 2, y2, y3);
}

// ---------------------------------------------------------------------------
// Attention: per (n, q): 8 heads x (1 query, 4 keys); output -> hi/lo planes.
// ---------------------------------------------------------------------------
__global__ __launch_bounds__(256)
void attn_split(const float* __restrict__ qh, const float* __restrict__ kh,
                const float* __restrict__ vh, __half* __restrict__ Ohi,
                __half* __restrict__ Olo)
{
    const int bq   = blockIdx.x;       // n*NQ + q
    const int n    = bq / NQ;
    const int q    = bq - n * NQ;
    const int h    = threadIdx.x >> 5;
    const int lane = threadIdx.x & 31;
    const int qr   = q / 12;
    const int qc   = q - qr * 12;

    const size_t qoff = (size_t)bq * E_DIM + h * 128 + lane * 4;
    const float4 qv = *(const float4*)(qh + qoff);

    float s[4];
    float4 vv[4];
    #pragma unroll
    for (int kk = 0; kk < 4; kk++) {
        const int t = (qr * 2 + (kk >> 1)) * 24 + qc * 2 + (kk & 1);
        const size_t krow = (size_t)(n * TN + t) * E_DIM + h * 128 + lane * 4;
        const float4 k4 = *(const float4*)(kh + krow);
        vv[kk] = *(const float4*)(vh + krow);
        float d = qv.x * k4.x + qv.y * k4.y + qv.z * k4.z + qv.w * k4.w;
        #pragma unroll
        for (int off = 16; off; off >>= 1) d += __shfl_xor_sync(0xffffffffu, d, off);
        s[kk] = d * 0.08838834764831845f;   // 1/sqrt(128)
    }
    const float m = fmaxf(fmaxf(s[0], s[1]), fmaxf(s[2], s[3]));
    float p[4], sum = 0.0f;
    #pragma unroll
    for (int kk = 0; kk < 4; kk++) { p[kk] = expf(s[kk] - m); sum += p[kk]; }
    const float inv = 1.0f / sum;
    float4 o = make_float4(0.f, 0.f, 0.f, 0.f);
    #pragma unroll
    for (int kk = 0; kk < 4; kk++) {
        const float pk = p[kk] * inv;
        o.x += pk * vv[kk].x; o.y += pk * vv[kk].y;
        o.z += pk * vv[kk].z; o.w += pk * vv[kk].w;
    }
    split_store2(Ohi, Olo, qoff,     o.x, o.y);
    split_store2(Ohi, Olo, qoff + 2, o.z, o.w);
}

// ---------------------------------------------------------------------------
// launch
// ---------------------------------------------------------------------------
extern "C" void kernel_launch(void* const* d_in, const int* in_sizes, int n_in,
                              void* d_out, int out_size)
{
    const float* x      = (const float*)d_in[0];
    const float* x_feat = (const float*)d_in[1];
    const float* w_q    = (const float*)d_in[2];
    const float* w_k1   = (const float*)d_in[3];
    const float* b_k1   = (const float*)d_in[4];
    const float* w_k2   = (const float*)d_in[5];
    const float* b_k2   = (const float*)d_in[6];
    const float* w_v1   = (const float*)d_in[7];
    const float* b_v1   = (const float*)d_in[8];
    const float* w_v2   = (const float*)d_in[9];
    const float* b_v2   = (const float*)d_in[10];
    const float* ln_q_w = (const float*)d_in[11];
    const float* ln_q_b = (const float*)d_in[12];
    const float* ln_k_w = (const float*)d_in[13];
    const float* ln_k_b = (const float*)d_in[14];
    const float* ln_v_w = (const float*)d_in[15];
    const float* ln_v_b = (const float*)d_in[16];
    const float* in_w   = (const float*)d_in[17];
    const float* in_b   = (const float*)d_in[18];
    const float* out_w  = (const float*)d_in[19];
    const float* out_b  = (const float*)d_in[20];
    float* out = (float*)d_out;

    __half *xf_h, *xf_l, *x_h, *x_l, *tmp_h, *tmp_l, *kn_h, *kn_l, *vn_h, *vn_l;
    __half *qn_h, *qn_l, *at_h, *at_l, *w_h, *w_l;
    float *key, *val, *qry, *qh, *kh, *vh;
    cudaGetSymbolAddress((void**)&xf_h, g_xf_h);  cudaGetSymbolAddress((void**)&xf_l, g_xf_l);
    cudaGetSymbolAddress((void**)&x_h,  g_x_h);   cudaGetSymbolAddress((void**)&x_l,  g_x_l);
    cudaGetSymbolAddress((void**)&tmp_h,g_tmp_h); cudaGetSymbolAddress((void**)&tmp_l,g_tmp_l);
    cudaGetSymbolAddress((void**)&kn_h, g_kn_h);  cudaGetSymbolAddress((void**)&kn_l, g_kn_l);
    cudaGetSymbolAddress((void**)&vn_h, g_vn_h);  cudaGetSymbolAddress((void**)&vn_l, g_vn_l);
    cudaGetSymbolAddress((void**)&qn_h, g_qn_h);  cudaGetSymbolAddress((void**)&qn_l, g_qn_l);
    cudaGetSymbolAddress((void**)&at_h, g_at_h);  cudaGetSymbolAddress((void**)&at_l, g_at_l);
    cudaGetSymbolAddress((void**)&w_h,  g_w_h);   cudaGetSymbolAddress((void**)&w_l,  g_w_l);
    cudaGetSymbolAddress((void**)&key,  g_key);   cudaGetSymbolAddress((void**)&val,  g_val);
    cudaGetSymbolAddress((void**)&qry,  g_qry);   cudaGetSymbolAddress((void**)&qh,   g_qh);
    cudaGetSymbolAddress((void**)&kh,   g_kh);    cudaGetSymbolAddress((void**)&vh,   g_vh);

    cudaFuncSetAttribute(gemm_f16x2<0>, cudaFuncAttributeMaxDynamicSharedMemorySize, GEMM_SMEM);
    cudaFuncSetAttribute(gemm_f16x2<1>, cudaFuncAttributeMaxDynamicSharedMemorySize, GEMM_SMEM);
    cudaFuncSetAttribute(gemm_f16x2<2>, cudaFuncAttributeMaxDynamicSharedMemorySize, GEMM_SMEM);

    dim3 blk(256);
    dim3 gridBig(E_DIM / 128, M_BIG / 128);   // (8, 288)
    dim3 gridSml(E_DIM / 128, M_SML / 128);   // (8, 72)

    // split inputs
    {
        int n4 = (int)((size_t)M_BIG * E_DIM / 4);
        split_f32<<<(n4 + 255) / 256, blk>>>((const float4*)x_feat, xf_h, xf_l, n4);
    }
    {
        int n4 = (int)((size_t)M_SML * E_DIM / 4);
        split_f32<<<(n4 + 255) / 256, blk>>>((const float4*)x, x_h, x_l, n4);
    }
    // split weights: slots 0..8
    {
        int n4 = (int)(WSLOT / 4);
        int g = (n4 + 255) / 256;
        split_f32<<<g, blk>>>((const float4*)w_q,  w_h + 0 * WSLOT, w_l + 0 * WSLOT, n4);
        split_f32<<<g, blk>>>((const float4*)w_k1, w_h + 1 * WSLOT, w_l + 1 * WSLOT, n4);
        split_f32<<<g, blk>>>((const float4*)w_k2, w_h + 2 * WSLOT, w_l + 2 * WSLOT, n4);
        split_f32<<<g, blk>>>((const float4*)w_v1, w_h + 3 * WSLOT, w_l + 3 * WSLOT, n4);
        split_f32<<<g, blk>>>((const float4*)w_v2, w_h + 4 * WSLOT, w_l + 4 * WSLOT, n4);
        split_f32<<<3 * g, blk>>>((const float4*)in_w, w_h + 5 * WSLOT, w_l + 5 * WSLOT, 3 * n4);
        split_f32<<<g, blk>>>((const float4*)out_w, w_h + 8 * WSLOT, w_l + 8 * WSLOT, n4);
    }

    // key path
    gemm_f16x2<2><<<gridBig, blk, GEMM_SMEM>>>(xf_h, xf_l, w_h + 1 * WSLOT, w_l + 1 * WSLOT,
                                               b_k1, nullptr, tmp_h, tmp_l);
    gemm_f16x2<1><<<gridBig, blk, GEMM_SMEM>>>(tmp_h, tmp_l, w_h + 2 * WSLOT, w_l + 2 * WSLOT,
                                               b_k2, key, nullptr, nullptr);
    ln_split<<<M_BIG, blk>>>(key, kn_h, kn_l, ln_k_w, ln_k_b);
    // value path
    gemm_f16x2<2><<<gridBig, blk, GEMM_SMEM>>>(xf_h, xf_l, w_h + 3 * WSLOT, w_l + 3 * WSLOT,
                                               b_v1, nullptr, tmp_h, tmp_l);
    gemm_f16x2<1><<<gridBig, blk, GEMM_SMEM>>>(tmp_h, tmp_l, w_h + 4 * WSLOT, w_l + 4 * WSLOT,
                                               b_v2, val, nullptr, nullptr);
    ln_split<<<M_BIG, blk>>>(val, vn_h, vn_l, ln_v_w, ln_v_b);
    // query path
    gemm_f16x2<0><<<gridSml, blk, GEMM_SMEM>>>(x_h, x_l, w_h + 0 * WSLOT, w_l + 0 * WSLOT,
                                               nullptr, qry, nullptr, nullptr);
    ln_split<<<M_SML, blk>>>(qry, qn_h, qn_l, ln_q_w, ln_q_b);
    // in-proj q/k/v
    gemm_f16x2<1><<<gridSml, blk, GEMM_SMEM>>>(qn_h, qn_l, w_h + 5 * WSLOT, w_l + 5 * WSLOT,
                                               in_b, qh, nullptr, nullptr);
    gemm_f16x2<1><<<gridBig, blk, GEMM_SMEM>>>(kn_h, kn_l, w_h + 6 * WSLOT, w_l + 6 * WSLOT,
                                               in_b + E_DIM, kh, nullptr, nullptr);
    gemm_f16x2<1><<<gridBig, blk, GEMM_SMEM>>>(vn_h, vn_l, w_h + 7 * WSLOT, w_l + 7 * WSLOT,
                                               in_b + 2 * E_DIM, vh, nullptr, nullptr);
    // attention (writes split att)
    attn_split<<<M_SML, blk>>>(qh, kh, vh, at_h, at_l);
    // out-proj -> d_out
    gemm_f16x2<1><<<gridSml, blk, GEMM_SMEM>>>(at_h, at_l, w_h + 8 * WSLOT, w_l + 8 * WSLOT,
                                               out_b, out, nullptr, nullptr);
}

// round 4
// speedup vs baseline: 2.4906x; 1.3405x over previous
#include <cuda_runtime.h>
#include <cuda_fp16.h>
#include <cstdint>
#include <cstddef>

// ---------------------------------------------------------------------------
// TokenPacker round 4: fp16 2-term split GEMMs on mma.sync m16n8k16.
// C = (Ah + Al) @ Bh^T  — corrects activation rounding; weight rounding error
// ~2^-12/sqrt-cancel ≈ 1.5e-4 rel, under the 1e-3 gate. 33% less mma work
// than round 2, 25% less smem/gmem traffic (no B_lo plane).
// ---------------------------------------------------------------------------

#define E_DIM 1024
#define NQ 144
#define TN 576
#define NB 64
#define M_BIG  (NB * TN)   // 36864
#define M_SML  (NB * NQ)   // 9216

#define WSLOT ((size_t)E_DIM * E_DIM)

// fp16 hi/lo activation planes
__device__ __half g_xf_h [(size_t)M_BIG * E_DIM];
__device__ __half g_xf_l [(size_t)M_BIG * E_DIM];
__device__ __half g_x_h  [(size_t)M_SML * E_DIM];
__device__ __half g_x_l  [(size_t)M_SML * E_DIM];
__device__ __half g_tmp_h[(size_t)M_BIG * E_DIM];
__device__ __half g_tmp_l[(size_t)M_BIG * E_DIM];
__device__ __half g_kn_h [(size_t)M_BIG * E_DIM];
__device__ __half g_kn_l [(size_t)M_BIG * E_DIM];
__device__ __half g_vn_h [(size_t)M_BIG * E_DIM];
__device__ __half g_vn_l [(size_t)M_BIG * E_DIM];
__device__ __half g_qn_h [(size_t)M_SML * E_DIM];
__device__ __half g_qn_l [(size_t)M_SML * E_DIM];
__device__ __half g_at_h [(size_t)M_SML * E_DIM];
__device__ __half g_at_l [(size_t)M_SML * E_DIM];
// fp16 weight slots (hi only): 0=wq 1=wk1 2=wk2 3=wv1 4=wv2 5,6,7=in_w 8=out_w
__device__ __half g_w_h[9 * WSLOT];
// fp32 scratch
__device__ float g_key[(size_t)M_BIG * E_DIM];
__device__ float g_val[(size_t)M_BIG * E_DIM];
__device__ float g_qry[(size_t)M_SML * E_DIM];
__device__ float g_qh [(size_t)M_SML * E_DIM];
__device__ float g_kh [(size_t)M_BIG * E_DIM];
__device__ float g_vh [(size_t)M_BIG * E_DIM];

// ---------------------------------------------------------------------------
// helpers
// ---------------------------------------------------------------------------
__device__ __forceinline__ void mma16(float* c, const uint32_t* a, const uint32_t* b) {
    asm volatile(
        "mma.sync.aligned.m16n8k16.row.col.f32.f16.f16.f32 "
        "{%0,%1,%2,%3}, {%4,%5,%6,%7}, {%8,%9}, {%0,%1,%2,%3};\n"
        : "+f"(c[0]), "+f"(c[1]), "+f"(c[2]), "+f"(c[3])
        : "r"(a[0]), "r"(a[1]), "r"(a[2]), "r"(a[3]), "r"(b[0]), "r"(b[1]));
}

__device__ __forceinline__ void cp_async16(void* smem, const void* gmem) {
    uint32_t s = (uint32_t)__cvta_generic_to_shared(smem);
    asm volatile("cp.async.ca.shared.global [%0], [%1], 16;\n" :: "r"(s), "l"(gmem));
}
__device__ __forceinline__ void cp_commit() { asm volatile("cp.async.commit_group;\n"); }
template <int N>
__device__ __forceinline__ void cp_wait() { asm volatile("cp.async.wait_group %0;\n" :: "n"(N)); }

__device__ __forceinline__ void split_store2(__half* __restrict__ hi, __half* __restrict__ lo,
                                             size_t off, float a, float b) {
    __half h0 = __float2half_rn(a), h1 = __float2half_rn(b);
    __half l0 = __float2half_rn(a - __half2float(h0));
    __half l1 = __float2half_rn(b - __half2float(h1));
    *(__half2*)(hi + off) = __halves2half2(h0, h1);
    *(__half2*)(lo + off) = __halves2half2(l0, l1);
}

__device__ __forceinline__ float gelu_exact(float x) {
    return 0.5f * x * (1.0f + erff(x * 0.7071067811865476f));
}

// ---------------------------------------------------------------------------
// split kernels
// ---------------------------------------------------------------------------
__global__ __launch_bounds__(256)
void split_f32(const float4* __restrict__ src, __half* __restrict__ hi,
               __half* __restrict__ lo, int n4)
{
    int i = blockIdx.x * blockDim.x + threadIdx.x;
    if (i < n4) {
        float4 v = src[i];
        size_t off = (size_t)i * 4;
        split_store2(hi, lo, off,     v.x, v.y);
        split_store2(hi, lo, off + 2, v.z, v.w);
    }
}

__global__ __launch_bounds__(256)
void cvt_f32_hi(const float4* __restrict__ src, __half* __restrict__ hi, int n4)
{
    int i = blockIdx.x * blockDim.x + threadIdx.x;
    if (i < n4) {
        float4 v = src[i];
        __half2 a = __halves2half2(__float2half_rn(v.x), __float2half_rn(v.y));
        __half2 b = __halves2half2(__float2half_rn(v.z), __float2half_rn(v.w));
        *(__half2*)(hi + (size_t)i * 4)     = a;
        *(__half2*)(hi + (size_t)i * 4 + 2) = b;
    }
}

// ---------------------------------------------------------------------------
// GEMM: C[M,1024] = (Ah+Al)[M,1024] @ Bh^T, 2 mma terms.
// MODE 0: fp32 out. MODE 1: fp32 + bias. MODE 2: gelu(+bias) -> hi/lo planes.
// BM=BN=128, BK=32, 256 thr, 8 warps (4x2), warp tile 32x64, cp.async dbl-buf.
// ---------------------------------------------------------------------------
#define BK 32
#define S16 40                 // halves per smem row (32 + 8 pad)
#define TILEH (128 * S16)      // halves per tile plane
#define GEMM_SMEM (2 * 3 * TILEH * 2)   // 61440 bytes

template<int MODE>
__global__ __launch_bounds__(256, 2)
void gemm_f16x2(const __half* __restrict__ Ah, const __half* __restrict__ Al,
                const __half* __restrict__ Bh,
                const float* __restrict__ bias,
                float* __restrict__ Cf,
                __half* __restrict__ Chi, __half* __restrict__ Clo)
{
    extern __shared__ __half sm[];
    const int tid  = threadIdx.x;
    const int lane = tid & 31;
    const int wid  = tid >> 5;
    const int wm   = (wid >> 1) * 32;
    const int wn   = (wid & 1) * 64;
    const int bm   = blockIdx.y;
    const int bn   = blockIdx.x;

    float acc[2][8][4];
    #pragma unroll
    for (int mt = 0; mt < 2; mt++)
        #pragma unroll
        for (int nt = 0; nt < 8; nt++)
            #pragma unroll
            for (int i = 0; i < 4; i++) acc[mt][nt][i] = 0.0f;

    auto load_tiles = [&](int kt, int buf) {
        const int k0 = kt * BK;
        __half* base = sm + buf * 3 * TILEH;
        #pragma unroll
        for (int t = 0; t < 2; t++) {
            int idx = tid + t * 256;          // 0..511
            int row = idx >> 2, c = idx & 3;  // c: 16B chunk (8 halves)
            size_t ga = (size_t)(bm * 128 + row) * E_DIM + k0 + c * 8;
            size_t gb = (size_t)(bn * 128 + row) * E_DIM + k0 + c * 8;
            uint32_t d = row * S16 + c * 8;
            cp_async16(base + d,             Ah + ga);
            cp_async16(base + TILEH + d,     Al + ga);
            cp_async16(base + 2 * TILEH + d, Bh + gb);
        }
    };

    load_tiles(0, 0);
    cp_commit();

    const int NKT = E_DIM / BK;  // 32
    for (int kt = 0; kt < NKT; kt++) {
        const int buf = kt & 1;
        if (kt + 1 < NKT) {
            load_tiles(kt + 1, buf ^ 1);
            cp_commit();
            cp_wait<1>();
        } else {
            cp_wait<0>();
        }
        __syncthreads();

        const __half* sAh = sm + buf * 3 * TILEH;
        const __half* sAl = sAh + TILEH;
        const __half* sBh = sAh + 2 * TILEH;

        #pragma unroll
        for (int ks = 0; ks < 2; ks++) {
            const int kb = ks * 16;
            uint32_t ah[2][4], al[2][4];
            #pragma unroll
            for (int mt = 0; mt < 2; mt++)
                #pragma unroll
                for (int i = 0; i < 4; i++) {
                    int row = wm + mt * 16 + (lane >> 2) + ((i & 1) << 3);
                    int col = kb + ((lane & 3) << 1) + ((i >> 1) << 3);
                    ah[mt][i] = *(const uint32_t*)(sAh + row * S16 + col);
                    al[mt][i] = *(const uint32_t*)(sAl + row * S16 + col);
                }
            #pragma unroll
            for (int nt = 0; nt < 8; nt++) {
                int n = wn + nt * 8 + (lane >> 2);
                int k = kb + ((lane & 3) << 1);
                uint32_t bh[2];
                bh[0] = *(const uint32_t*)(sBh + n * S16 + k);
                bh[1] = *(const uint32_t*)(sBh + n * S16 + k + 8);
                #pragma unroll
                for (int mt = 0; mt < 2; mt++) {
                    mma16(acc[mt][nt], ah[mt], bh);
                    mma16(acc[mt][nt], al[mt], bh);
                }
            }
        }
        __syncthreads();
    }

    // epilogue
    #pragma unroll
    for (int mt = 0; mt < 2; mt++) {
        #pragma unroll
        for (int nt = 0; nt < 8; nt++) {
            int row0 = bm * 128 + wm + mt * 16 + (lane >> 2);
            int col  = bn * 128 + wn + nt * 8 + ((lane & 3) << 1);
            float bv0 = 0.0f, bv1 = 0.0f;
            if (MODE != 0) { bv0 = bias[col]; bv1 = bias[col + 1]; }
            float c0 = acc[mt][nt][0] + bv0;
            float c1 = acc[mt][nt][1] + bv1;
            float c2 = acc[mt][nt][2] + bv0;
            float c3 = acc[mt][nt][3] + bv1;
            if (MODE == 2) {
                c0 = gelu_exact(c0); c1 = gelu_exact(c1);
                c2 = gelu_exact(c2); c3 = gelu_exact(c3);
                size_t o0 = (size_t)row0 * E_DIM + col;
                size_t o1 = (size_t)(row0 + 8) * E_DIM + col;
                split_store2(Chi, Clo, o0, c0, c1);
                split_store2(Chi, Clo, o1, c2, c3);
            } else {
                *(float2*)(Cf + (size_t)row0 * E_DIM + col)       = make_float2(c0, c1);
                *(float2*)(Cf + (size_t)(row0 + 8) * E_DIM + col) = make_float2(c2, c3);
            }
        }
    }
}

// ---------------------------------------------------------------------------
// LayerNorm over last dim (1024) -> fp16 hi/lo planes. 256 thr per row.
// ---------------------------------------------------------------------------
__global__ __launch_bounds__(256)
void ln_split(const float* __restrict__ X, __half* __restrict__ Hi, __half* __restrict__ Lo,
              const float* __restrict__ w, const float* __restrict__ b)
{
    const size_t row = blockIdx.x;
    const float4* xp = (const float4*)(X + row * E_DIM);
    const int tid  = threadIdx.x;
    const int lane = tid & 31;
    const int wid  = tid >> 5;

    float4 v = xp[tid];
    float s  = v.x + v.y + v.z + v.w;
    float ss = v.x * v.x + v.y * v.y + v.z * v.z + v.w * v.w;
    #pragma unroll
    for (int off = 16; off; off >>= 1) {
        s  += __shfl_xor_sync(0xffffffffu, s, off);
        ss += __shfl_xor_sync(0xffffffffu, ss, off);
    }
    __shared__ float rs[8], rss[8];
    if (lane == 0) { rs[wid] = s; rss[wid] = ss; }
    __syncthreads();
    float ts = 0.0f, tss = 0.0f;
    #pragma unroll
    for (int i = 0; i < 8; i++) { ts += rs[i]; tss += rss[i]; }
    const float mean = ts * (1.0f / 1024.0f);
    const float var  = tss * (1.0f / 1024.0f) - mean * mean;
    const float inv  = rsqrtf(var + 1e-6f);

    const float4 w4 = ((const float4*)w)[tid];
    const float4 b4 = ((const float4*)b)[tid];
    float y0 = (v.x - mean) * inv * w4.x + b4.x;
    float y1 = (v.y - mean) * inv * w4.y + b4.y;
    float y2 = (v.z - mean) * inv * w4.z + b4.z;
    float y3 = (v.w - mean) * inv * w4.w + b4.w;
    size_t off = row * E_DIM + (size_t)tid * 4;
    split_store2(Hi, Lo, off,     y0, y1);
    split_store2(Hi, Lo, off + 2, y2, y3);
}

// ---------------------------------------------------------------------------
// Attention: per (n, q): 8 heads x (1 query, 4 keys); output -> hi/lo planes.
// ---------------------------------------------------------------------------
__global__ __launch_bounds__(256)
void attn_split(const float* __restrict__ qh, const float* __restrict__ kh,
                const float* __restrict__ vh, __half* __restrict__ Ohi,
                __half* __restrict__ Olo)
{
    const int bq   = blockIdx.x;
    const int n    = bq / NQ;
    const int q    = bq - n * NQ;
    const int h    = threadIdx.x >> 5;
    const int lane = threadIdx.x & 31;
    const int qr   = q / 12;
    const int qc   = q - qr * 12;

    const size_t qoff = (size_t)bq * E_DIM + h * 128 + lane * 4;
    const float4 qv = *(const float4*)(qh + qoff);

    float s[4];
    float4 vv[4];
    #pragma unroll
    for (int kk = 0; kk < 4; kk++) {
        const int t = (qr * 2 + (kk >> 1)) * 24 + qc * 2 + (kk & 1);
        const size_t krow = (size_t)(n * TN + t) * E_DIM + h * 128 + lane * 4;
        const float4 k4 = *(const float4*)(kh + krow);
        vv[kk] = *(const float4*)(vh + krow);
        float d = qv.x * k4.x + qv.y * k4.y + qv.z * k4.z + qv.w * k4.w;
        #pragma unroll
        for (int off = 16; off; off >>= 1) d += __shfl_xor_sync(0xffffffffu, d, off);
        s[kk] = d * 0.08838834764831845f;
    }
    const float m = fmaxf(fmaxf(s[0], s[1]), fmaxf(s[2], s[3]));
    float p[4], sum = 0.0f;
    #pragma unroll
    for (int kk = 0; kk < 4; kk++) { p[kk] = expf(s[kk] - m); sum += p[kk]; }
    const float inv = 1.0f / sum;
    float4 o = make_float4(0.f, 0.f, 0.f, 0.f);
    #pragma unroll
    for (int kk = 0; kk < 4; kk++) {
        const float pk = p[kk] * inv;
        o.x += pk * vv[kk].x; o.y += pk * vv[kk].y;
        o.z += pk * vv[kk].z; o.w += pk * vv[kk].w;
    }
    split_store2(Ohi, Olo, qoff,     o.x, o.y);
    split_store2(Ohi, Olo, qoff + 2, o.z, o.w);
}

// ---------------------------------------------------------------------------
// launch
// ---------------------------------------------------------------------------
extern "C" void kernel_launch(void* const* d_in, const int* in_sizes, int n_in,
                              void* d_out, int out_size)
{
    const float* x      = (const float*)d_in[0];
    const float* x_feat = (const float*)d_in[1];
    const float* w_q    = (const float*)d_in[2];
    const float* w_k1   = (const float*)d_in[3];
    const float* b_k1   = (const float*)d_in[4];
    const float* w_k2   = (const float*)d_in[5];
    const float* b_k2   = (const float*)d_in[6];
    const float* w_v1   = (const float*)d_in[7];
    const float* b_v1   = (const float*)d_in[8];
    const float* w_v2   = (const float*)d_in[9];
    const float* b_v2   = (const float*)d_in[10];
    const float* ln_q_w = (const float*)d_in[11];
    const float* ln_q_b = (const float*)d_in[12];
    const float* ln_k_w = (const float*)d_in[13];
    const float* ln_k_b = (const float*)d_in[14];
    const float* ln_v_w = (const float*)d_in[15];
    const float* ln_v_b = (const float*)d_in[16];
    const float* in_w   = (const float*)d_in[17];
    const float* in_b   = (const float*)d_in[18];
    const float* out_w  = (const float*)d_in[19];
    const float* out_b  = (const float*)d_in[20];
    float* out = (float*)d_out;

    __half *xf_h, *xf_l, *x_h, *x_l, *tmp_h, *tmp_l, *kn_h, *kn_l, *vn_h, *vn_l;
    __half *qn_h, *qn_l, *at_h, *at_l, *w_h;
    float *key, *val, *qry, *qh, *kh, *vh;
    cudaGetSymbolAddress((void**)&xf_h, g_xf_h);  cudaGetSymbolAddress((void**)&xf_l, g_xf_l);
    cudaGetSymbolAddress((void**)&x_h,  g_x_h);   cudaGetSymbolAddress((void**)&x_l,  g_x_l);
    cudaGetSymbolAddress((void**)&tmp_h,g_tmp_h); cudaGetSymbolAddress((void**)&tmp_l,g_tmp_l);
    cudaGetSymbolAddress((void**)&kn_h, g_kn_h);  cudaGetSymbolAddress((void**)&kn_l, g_kn_l);
    cudaGetSymbolAddress((void**)&vn_h, g_vn_h);  cudaGetSymbolAddress((void**)&vn_l, g_vn_l);
    cudaGetSymbolAddress((void**)&qn_h, g_qn_h);  cudaGetSymbolAddress((void**)&qn_l, g_qn_l);
    cudaGetSymbolAddress((void**)&at_h, g_at_h);  cudaGetSymbolAddress((void**)&at_l, g_at_l);
    cudaGetSymbolAddress((void**)&w_h,  g_w_h);
    cudaGetSymbolAddress((void**)&key,  g_key);   cudaGetSymbolAddress((void**)&val,  g_val);
    cudaGetSymbolAddress((void**)&qry,  g_qry);   cudaGetSymbolAddress((void**)&qh,   g_qh);
    cudaGetSymbolAddress((void**)&kh,   g_kh);    cudaGetSymbolAddress((void**)&vh,   g_vh);

    cudaFuncSetAttribute(gemm_f16x2<0>, cudaFuncAttributeMaxDynamicSharedMemorySize, GEMM_SMEM);
    cudaFuncSetAttribute(gemm_f16x2<1>, cudaFuncAttributeMaxDynamicSharedMemorySize, GEMM_SMEM);
    cudaFuncSetAttribute(gemm_f16x2<2>, cudaFuncAttributeMaxDynamicSharedMemorySize, GEMM_SMEM);

    dim3 blk(256);
    dim3 gridBig(E_DIM / 128, M_BIG / 128);   // (8, 288)
    dim3 gridSml(E_DIM / 128, M_SML / 128);   // (8, 72)

    // split inputs (hi+lo — they are A operands)
    {
        int n4 = (int)((size_t)M_BIG * E_DIM / 4);
        split_f32<<<(n4 + 255) / 256, blk>>>((const float4*)x_feat, xf_h, xf_l, n4);
    }
    {
        int n4 = (int)((size_t)M_SML * E_DIM / 4);
        split_f32<<<(n4 + 255) / 256, blk>>>((const float4*)x, x_h, x_l, n4);
    }
    // convert weights (hi only — B operands)
    {
        int n4 = (int)(WSLOT / 4);
        int g = (n4 + 255) / 256;
        cvt_f32_hi<<<g, blk>>>((const float4*)w_q,  w_h + 0 * WSLOT, n4);
        cvt_f32_hi<<<g, blk>>>((const float4*)w_k1, w_h + 1 * WSLOT, n4);
        cvt_f32_hi<<<g, blk>>>((const float4*)w_k2, w_h + 2 * WSLOT, n4);
        cvt_f32_hi<<<g, blk>>>((const float4*)w_v1, w_h + 3 * WSLOT, n4);
        cvt_f32_hi<<<g, blk>>>((const float4*)w_v2, w_h + 4 * WSLOT, n4);
        cvt_f32_hi<<<3 * g, blk>>>((const float4*)in_w, w_h + 5 * WSLOT, 3 * n4);
        cvt_f32_hi<<<g, blk>>>((const float4*)out_w, w_h + 8 * WSLOT, n4);
    }

    // key path
    gemm_f16x2<2><<<gridBig, blk, GEMM_SMEM>>>(xf_h, xf_l, w_h + 1 * WSLOT,
                                               b_k1, nullptr, tmp_h, tmp_l);
    gemm_f16x2<1><<<gridBig, blk, GEMM_SMEM>>>(tmp_h, tmp_l, w_h + 2 * WSLOT,
                                               b_k2, key, nullptr, nullptr);
    ln_split<<<M_BIG, blk>>>(key, kn_h, kn_l, ln_k_w, ln_k_b);
    // value path
    gemm_f16x2<2><<<gridBig, blk, GEMM_SMEM>>>(xf_h, xf_l, w_h + 3 * WSLOT,
                                               b_v1, nullptr, tmp_h, tmp_l);
    gemm_f16x2<1><<<gridBig, blk, GEMM_SMEM>>>(tmp_h, tmp_l, w_h + 4 * WSLOT,
                                               b_v2, val, nullptr, nullptr);
    ln_split<<<M_BIG, blk>>>(val, vn_h, vn_l, ln_v_w, ln_v_b);
    // query path
    gemm_f16x2<0><<<gridSml, blk, GEMM_SMEM>>>(x_h, x_l, w_h + 0 * WSLOT,
                                               nullptr, qry, nullptr, nullptr);
    ln_split<<<M_SML, blk>>>(qry, qn_h, qn_l, ln_q_w, ln_q_b);
    // in-proj q/k/v
    gemm_f16x2<1><<<gridSml, blk, GEMM_SMEM>>>(qn_h, qn_l, w_h + 5 * WSLOT,
                                               in_b, qh, nullptr, nullptr);
    gemm_f16x2<1><<<gridBig, blk, GEMM_SMEM>>>(kn_h, kn_l, w_h + 6 * WSLOT,
                                               in_b + E_DIM, kh, nullptr, nullptr);
    gemm_f16x2<1><<<gridBig, blk, GEMM_SMEM>>>(vn_h, vn_l, w_h + 7 * WSLOT,
                                               in_b + 2 * E_DIM, vh, nullptr, nullptr);
    // attention
    attn_split<<<M_SML, blk>>>(qh, kh, vh, at_h, at_l);
    // out-proj -> d_out
    gemm_f16x2<1><<<gridSml, blk, GEMM_SMEM>>>(at_h, at_l, w_h + 8 * WSLOT,
                                               out_b, out, nullptr, nullptr);
}

// round 5
// speedup vs baseline: 2.7779x; 1.1153x over previous
#include <cuda_runtime.h>
#include <cuda_fp16.h>
#include <cstdint>
#include <cstddef>

// ---------------------------------------------------------------------------
// TokenPacker round 5: 2-term fp16 split GEMM, ldmatrix fragment loads,
// 3-stage cp.async pipeline (load-ahead-2), one syncthreads per k-tile.
// ---------------------------------------------------------------------------

#define E_DIM 1024
#define NQ 144
#define TN 576
#define NB 64
#define M_BIG  (NB * TN)   // 36864
#define M_SML  (NB * NQ)   // 9216

#define WSLOT ((size_t)E_DIM * E_DIM)

// fp16 hi/lo activation planes
__device__ __half g_xf_h [(size_t)M_BIG * E_DIM];
__device__ __half g_xf_l [(size_t)M_BIG * E_DIM];
__device__ __half g_x_h  [(size_t)M_SML * E_DIM];
__device__ __half g_x_l  [(size_t)M_SML * E_DIM];
__device__ __half g_tmp_h[(size_t)M_BIG * E_DIM];
__device__ __half g_tmp_l[(size_t)M_BIG * E_DIM];
__device__ __half g_kn_h [(size_t)M_BIG * E_DIM];
__device__ __half g_kn_l [(size_t)M_BIG * E_DIM];
__device__ __half g_vn_h [(size_t)M_BIG * E_DIM];
__device__ __half g_vn_l [(size_t)M_BIG * E_DIM];
__device__ __half g_qn_h [(size_t)M_SML * E_DIM];
__device__ __half g_qn_l [(size_t)M_SML * E_DIM];
__device__ __half g_at_h [(size_t)M_SML * E_DIM];
__device__ __half g_at_l [(size_t)M_SML * E_DIM];
// fp16 weight slots (hi only): 0=wq 1=wk1 2=wk2 3=wv1 4=wv2 5,6,7=in_w 8=out_w
__device__ __half g_w_h[9 * WSLOT];
// fp32 scratch
__device__ float g_key[(size_t)M_BIG * E_DIM];
__device__ float g_val[(size_t)M_BIG * E_DIM];
__device__ float g_qry[(size_t)M_SML * E_DIM];
__device__ float g_qh [(size_t)M_SML * E_DIM];
__device__ float g_kh [(size_t)M_BIG * E_DIM];
__device__ float g_vh [(size_t)M_BIG * E_DIM];

// ---------------------------------------------------------------------------
// helpers
// ---------------------------------------------------------------------------
__device__ __forceinline__ void mma16(float* c, const uint32_t* a, const uint32_t* b) {
    asm volatile(
        "mma.sync.aligned.m16n8k16.row.col.f32.f16.f16.f32 "
        "{%0,%1,%2,%3}, {%4,%5,%6,%7}, {%8,%9}, {%0,%1,%2,%3};\n"
        : "+f"(c[0]), "+f"(c[1]), "+f"(c[2]), "+f"(c[3])
        : "r"(a[0]), "r"(a[1]), "r"(a[2]), "r"(a[3]), "r"(b[0]), "r"(b[1]));
}

__device__ __forceinline__ void ldsm_x4(uint32_t* r, uint32_t addr) {
    asm volatile("ldmatrix.sync.aligned.m8n8.x4.shared.b16 {%0,%1,%2,%3}, [%4];"
        : "=r"(r[0]), "=r"(r[1]), "=r"(r[2]), "=r"(r[3]) : "r"(addr));
}

__device__ __forceinline__ void cp_async16(uint32_t saddr, const void* gmem) {
    asm volatile("cp.async.ca.shared.global [%0], [%1], 16;\n" :: "r"(saddr), "l"(gmem));
}
__device__ __forceinline__ void cp_commit() { asm volatile("cp.async.commit_group;\n"); }
template <int N>
__device__ __forceinline__ void cp_wait() { asm volatile("cp.async.wait_group %0;\n" :: "n"(N)); }

__device__ __forceinline__ void split_store2(__half* __restrict__ hi, __half* __restrict__ lo,
                                             size_t off, float a, float b) {
    __half h0 = __float2half_rn(a), h1 = __float2half_rn(b);
    __half l0 = __float2half_rn(a - __half2float(h0));
    __half l1 = __float2half_rn(b - __half2float(h1));
    *(__half2*)(hi + off) = __halves2half2(h0, h1);
    *(__half2*)(lo + off) = __halves2half2(l0, l1);
}

__device__ __forceinline__ float gelu_exact(float x) {
    return 0.5f * x * (1.0f + erff(x * 0.7071067811865476f));
}

// ---------------------------------------------------------------------------
// split kernels
// ---------------------------------------------------------------------------
__global__ __launch_bounds__(256)
void split_f32(const float4* __restrict__ src, __half* __restrict__ hi,
               __half* __restrict__ lo, int n4)
{
    int i = blockIdx.x * blockDim.x + threadIdx.x;
    if (i < n4) {
        float4 v = src[i];
        size_t off = (size_t)i * 4;
        split_store2(hi, lo, off,     v.x, v.y);
        split_store2(hi, lo, off + 2, v.z, v.w);
    }
}

__global__ __launch_bounds__(256)
void cvt_f32_hi(const float4* __restrict__ src, __half* __restrict__ hi, int n4)
{
    int i = blockIdx.x * blockDim.x + threadIdx.x;
    if (i < n4) {
        float4 v = src[i];
        __half2 a = __halves2half2(__float2half_rn(v.x), __float2half_rn(v.y));
        __half2 b = __halves2half2(__float2half_rn(v.z), __float2half_rn(v.w));
        *(__half2*)(hi + (size_t)i * 4)     = a;
        *(__half2*)(hi + (size_t)i * 4 + 2) = b;
    }
}

// ---------------------------------------------------------------------------
// GEMM: C[M,1024] = (Ah+Al)[M,1024] @ Bh^T, 2 mma terms, ldmatrix, 3 stages.
// MODE 0: fp32 out. MODE 1: fp32 + bias. MODE 2: gelu(+bias) -> hi/lo planes.
// BM=BN=128, BK=32, 256 thr, 8 warps (4x2), warp tile 32x64.
// ---------------------------------------------------------------------------
#define BK 32
#define S16 40                        // halves per smem row (32 + 8 pad)
#define PLANE_B (128 * S16 * 2)       // 10240 bytes per plane
#define STAGE_B (3 * PLANE_B)         // 30720 bytes per stage (Ah, Al, Bh)
#define NSTAGE 3
#define GEMM_SMEM (NSTAGE * STAGE_B)  // 92160 bytes
#define NKT (E_DIM / BK)              // 32

template<int MODE>
__global__ __launch_bounds__(256, 2)
void gemm_f16x2(const __half* __restrict__ Ah, const __half* __restrict__ Al,
                const __half* __restrict__ Bh,
                const float* __restrict__ bias,
                float* __restrict__ Cf,
                __half* __restrict__ Chi, __half* __restrict__ Clo)
{
    extern __shared__ __align__(128) char smraw[];
    const uint32_t smem_base = (uint32_t)__cvta_generic_to_shared(smraw);
    const int tid  = threadIdx.x;
    const int lane = tid & 31;
    const int wid  = tid >> 5;
    const int wm   = (wid >> 1) * 32;   // warp M offset
    const int wn   = (wid & 1) * 64;    // warp N offset
    const int bm   = blockIdx.y;
    const int bn   = blockIdx.x;

    float acc[2][8][4];
    #pragma unroll
    for (int mt = 0; mt < 2; mt++)
        #pragma unroll
        for (int nt = 0; nt < 8; nt++)
            #pragma unroll
            for (int i = 0; i < 4; i++) acc[mt][nt][i] = 0.0f;

    // ldmatrix per-lane byte offsets (within a plane), loop-invariant
    uint32_t aoff[2], boff[4];
    #pragma unroll
    for (int mt = 0; mt < 2; mt++)
        aoff[mt] = ((wm + mt * 16 + (lane & 15)) * S16 + ((lane >> 4) << 3)) * 2;
    #pragma unroll
    for (int j = 0; j < 4; j++)
        boff[j] = ((wn + (2 * j + ((lane >> 4) & 1)) * 8 + (lane & 7)) * S16
                   + (((lane >> 3) & 1) << 3)) * 2;

    // cp.async tile loader: 3 planes x 128 rows x 4 chunks(16B) = 1536, 6/thread
    const int lrowA = (tid & 511) >> 2;   // reused
    auto load_tiles = [&](int kt, int stg) {
        const int k0 = kt * BK;
        const uint32_t base = smem_base + stg * STAGE_B;
        #pragma unroll
        for (int t = 0; t < 4; t++) {           // planes 0,1 (Ah, Al)
            int idx = tid + t * 256;            // 0..1023
            int plane = idx >> 9;
            int rem = idx & 511;
            int row = rem >> 2, c = rem & 3;
            const __half* src = (plane ? Al : Ah)
                              + (size_t)(bm * 128 + row) * E_DIM + k0 + c * 8;
            cp_async16(base + plane * PLANE_B + row * (S16 * 2) + c * 16, src);
        }
        #pragma unroll
        for (int t = 0; t < 2; t++) {           // plane 2 (Bh)
            int idx = tid + t * 256;            // 0..511
            int row = idx >> 2, c = idx & 3;
            const __half* src = Bh + (size_t)(bn * 128 + row) * E_DIM + k0 + c * 8;
            cp_async16(base + 2 * PLANE_B + row * (S16 * 2) + c * 16, src);
        }
    };

    load_tiles(0, 0); cp_commit();
    load_tiles(1, 1); cp_commit();

    int stg = 0;
    for (int kt = 0; kt < NKT; kt++) {
        cp_wait<1>();            // stage kt ready (kt+1 still in flight)
        __syncthreads();         // all threads done reading stage (kt-1)%3 == (kt+2)%3
        if (kt + 2 < NKT) {
            int s2 = stg + 2; if (s2 >= NSTAGE) s2 -= NSTAGE;
            load_tiles(kt + 2, s2);
        }
        cp_commit();             // empty group ok near the end; keeps counts aligned

        const uint32_t sA  = smem_base + stg * STAGE_B;
        const uint32_t sAl = sA + PLANE_B;
        const uint32_t sB  = sA + 2 * PLANE_B;

        #pragma unroll
        for (int ks = 0; ks < 2; ks++) {
            const uint32_t kbb = ks * 16 * 2;   // byte offset for k half-step
            uint32_t ah0[4], ah1[4], al0[4], al1[4];
            ldsm_x4(ah0, sA  + aoff[0] + kbb);
            ldsm_x4(ah1, sA  + aoff[1] + kbb);
            ldsm_x4(al0, sAl + aoff[0] + kbb);
            ldsm_x4(al1, sAl + aoff[1] + kbb);
            uint32_t bb[4][4];                   // bb[j] = {b(2j,0),b(2j,1),b(2j+1,0),b(2j+1,1)}
            #pragma unroll
            for (int j = 0; j < 4; j++)
                ldsm_x4(bb[j], sB + boff[j] + kbb);
            #pragma unroll
            for (int nt = 0; nt < 8; nt++) {
                const uint32_t* bp = &bb[nt >> 1][(nt & 1) * 2];
                mma16(acc[0][nt], ah0, bp);
                mma16(acc[0][nt], al0, bp);
                mma16(acc[1][nt], ah1, bp);
                mma16(acc[1][nt], al1, bp);
            }
        }
        stg++; if (stg >= NSTAGE) stg -= NSTAGE;
    }

    // epilogue
    #pragma unroll
    for (int mt = 0; mt < 2; mt++) {
        #pragma unroll
        for (int nt = 0; nt < 8; nt++) {
            int row0 = bm * 128 + wm + mt * 16 + (lane >> 2);
            int col  = bn * 128 + wn + nt * 8 + ((lane & 3) << 1);
            float bv0 = 0.0f, bv1 = 0.0f;
            if (MODE != 0) { bv0 = bias[col]; bv1 = bias[col + 1]; }
            float c0 = acc[mt][nt][0] + bv0;
            float c1 = acc[mt][nt][1] + bv1;
            float c2 = acc[mt][nt][2] + bv0;
            float c3 = acc[mt][nt][3] + bv1;
            if (MODE == 2) {
                c0 = gelu_exact(c0); c1 = gelu_exact(c1);
                c2 = gelu_exact(c2); c3 = gelu_exact(c3);
                size_t o0 = (size_t)row0 * E_DIM + col;
                size_t o1 = (size_t)(row0 + 8) * E_DIM + col;
                split_store2(Chi, Clo, o0, c0, c1);
                split_store2(Chi, Clo, o1, c2, c3);
            } else {
                *(float2*)(Cf + (size_t)row0 * E_DIM + col)       = make_float2(c0, c1);
                *(float2*)(Cf + (size_t)(row0 + 8) * E_DIM + col) = make_float2(c2, c3);
            }
        }
    }
}

// ---------------------------------------------------------------------------
// LayerNorm over last dim (1024) -> fp16 hi/lo planes. 256 thr per row.
// ---------------------------------------------------------------------------
__global__ __launch_bounds__(256)
void ln_split(const float* __restrict__ X, __half* __restrict__ Hi, __half* __restrict__ Lo,
              const float* __restrict__ w, const float* __restrict__ b)
{
    const size_t row = blockIdx.x;
    const float4* xp = (const float4*)(X + row * E_DIM);
    const int tid  = threadIdx.x;
    const int lane = tid & 31;
    const int wid  = tid >> 5;

    float4 v = xp[tid];
    float s  = v.x + v.y + v.z + v.w;
    float ss = v.x * v.x + v.y * v.y + v.z * v.z + v.w * v.w;
    #pragma unroll
    for (int off = 16; off; off >>= 1) {
        s  += __shfl_xor_sync(0xffffffffu, s, off);
        ss += __shfl_xor_sync(0xffffffffu, ss, off);
    }
    __shared__ float rs[8], rss[8];
    if (lane == 0) { rs[wid] = s; rss[wid] = ss; }
    __syncthreads();
    float ts = 0.0f, tss = 0.0f;
    #pragma unroll
    for (int i = 0; i < 8; i++) { ts += rs[i]; tss += rss[i]; }
    const float mean = ts * (1.0f / 1024.0f);
    const float var  = tss * (1.0f / 1024.0f) - mean * mean;
    const float inv  = rsqrtf(var + 1e-6f);

    const float4 w4 = ((const float4*)w)[tid];
    const float4 b4 = ((const float4*)b)[tid];
    float y0 = (v.x - mean) * inv * w4.x + b4.x;
    float y1 = (v.y - mean) * inv * w4.y + b4.y;
    float y2 = (v.z - mean) * inv * w4.z + b4.z;
    float y3 = (v.w - mean) * inv * w4.w + b4.w;
    size_t off = row * E_DIM + (size_t)tid * 4;
    split_store2(Hi, Lo, off,     y0, y1);
    split_store2(Hi, Lo, off + 2, y2, y3);
}

// ---------------------------------------------------------------------------
// Attention: per (n, q): 8 heads x (1 query, 4 keys); output -> hi/lo planes.
// ---------------------------------------------------------------------------
__global__ __launch_bounds__(256)
void attn_split(const float* __restrict__ qh, const float* __restrict__ kh,
                const float* __restrict__ vh, __half* __restrict__ Ohi,
                __half* __restrict__ Olo)
{
    const int bq   = blockIdx.x;
    const int n    = bq / NQ;
    const int q    = bq - n * NQ;
    const int h    = threadIdx.x >> 5;
    const int lane = threadIdx.x & 31;
    const int qr   = q / 12;
    const int qc   = q - qr * 12;

    const size_t qoff = (size_t)bq * E_DIM + h * 128 + lane * 4;
    const float4 qv = *(const float4*)(qh + qoff);

    float s[4];
    float4 vv[4];
    #pragma unroll
    for (int kk = 0; kk < 4; kk++) {
        const int t = (qr * 2 + (kk >> 1)) * 24 + qc * 2 + (kk & 1);
        const size_t krow = (size_t)(n * TN + t) * E_DIM + h * 128 + lane * 4;
        const float4 k4 = *(const float4*)(kh + krow);
        vv[kk] = *(const float4*)(vh + krow);
        float d = qv.x * k4.x + qv.y * k4.y + qv.z * k4.z + qv.w * k4.w;
        #pragma unroll
        for (int off = 16; off; off >>= 1) d += __shfl_xor_sync(0xffffffffu, d, off);
        s[kk] = d * 0.08838834764831845f;
    }
    const float m = fmaxf(fmaxf(s[0], s[1]), fmaxf(s[2], s[3]));
    float p[4], sum = 0.0f;
    #pragma unroll
    for (int kk = 0; kk < 4; kk++) { p[kk] = expf(s[kk] - m); sum += p[kk]; }
    const float inv = 1.0f / sum;
    float4 o = make_float4(0.f, 0.f, 0.f, 0.f);
    #pragma unroll
    for (int kk = 0; kk < 4; kk++) {
        const float pk = p[kk] * inv;
        o.x += pk * vv[kk].x; o.y += pk * vv[kk].y;
        o.z += pk * vv[kk].z; o.w += pk * vv[kk].w;
    }
    split_store2(Ohi, Olo, qoff,     o.x, o.y);
    split_store2(Ohi, Olo, qoff + 2, o.z, o.w);
}

// ---------------------------------------------------------------------------
// launch
// ---------------------------------------------------------------------------
extern "C" void kernel_launch(void* const* d_in, const int* in_sizes, int n_in,
                              void* d_out, int out_size)
{
    const float* x      = (const float*)d_in[0];
    const float* x_feat = (const float*)d_in[1];
    const float* w_q    = (const float*)d_in[2];
    const float* w_k1   = (const float*)d_in[3];
    const float* b_k1   = (const float*)d_in[4];
    const float* w_k2   = (const float*)d_in[5];
    const float* b_k2   = (const float*)d_in[6];
    const float* w_v1   = (const float*)d_in[7];
    const float* b_v1   = (const float*)d_in[8];
    const float* w_v2   = (const float*)d_in[9];
    const float* b_v2   = (const float*)d_in[10];
    const float* ln_q_w = (const float*)d_in[11];
    const float* ln_q_b = (const float*)d_in[12];
    const float* ln_k_w = (const float*)d_in[13];
    const float* ln_k_b = (const float*)d_in[14];
    const float* ln_v_w = (const float*)d_in[15];
    const float* ln_v_b = (const float*)d_in[16];
    const float* in_w   = (const float*)d_in[17];
    const float* in_b   = (const float*)d_in[18];
    const float* out_w  = (const float*)d_in[19];
    const float* out_b  = (const float*)d_in[20];
    float* out = (float*)d_out;

    __half *xf_h, *xf_l, *x_h, *x_l, *tmp_h, *tmp_l, *kn_h, *kn_l, *vn_h, *vn_l;
    __half *qn_h, *qn_l, *at_h, *at_l, *w_h;
    float *key, *val, *qry, *qh, *kh, *vh;
    cudaGetSymbolAddress((void**)&xf_h, g_xf_h);  cudaGetSymbolAddress((void**)&xf_l, g_xf_l);
    cudaGetSymbolAddress((void**)&x_h,  g_x_h);   cudaGetSymbolAddress((void**)&x_l,  g_x_l);
    cudaGetSymbolAddress((void**)&tmp_h,g_tmp_h); cudaGetSymbolAddress((void**)&tmp_l,g_tmp_l);
    cudaGetSymbolAddress((void**)&kn_h, g_kn_h);  cudaGetSymbolAddress((void**)&kn_l, g_kn_l);
    cudaGetSymbolAddress((void**)&vn_h, g_vn_h);  cudaGetSymbolAddress((void**)&vn_l, g_vn_l);
    cudaGetSymbolAddress((void**)&qn_h, g_qn_h);  cudaGetSymbolAddress((void**)&qn_l, g_qn_l);
    cudaGetSymbolAddress((void**)&at_h, g_at_h);  cudaGetSymbolAddress((void**)&at_l, g_at_l);
    cudaGetSymbolAddress((void**)&w_h,  g_w_h);
    cudaGetSymbolAddress((void**)&key,  g_key);   cudaGetSymbolAddress((void**)&val,  g_val);
    cudaGetSymbolAddress((void**)&qry,  g_qry);   cudaGetSymbolAddress((void**)&qh,   g_qh);
    cudaGetSymbolAddress((void**)&kh,   g_kh);    cudaGetSymbolAddress((void**)&vh,   g_vh);

    cudaFuncSetAttribute(gemm_f16x2<0>, cudaFuncAttributeMaxDynamicSharedMemorySize, GEMM_SMEM);
    cudaFuncSetAttribute(gemm_f16x2<1>, cudaFuncAttributeMaxDynamicSharedMemorySize, GEMM_SMEM);
    cudaFuncSetAttribute(gemm_f16x2<2>, cudaFuncAttributeMaxDynamicSharedMemorySize, GEMM_SMEM);

    dim3 blk(256);
    dim3 gridBig(E_DIM / 128, M_BIG / 128);   // (8, 288)
    dim3 gridSml(E_DIM / 128, M_SML / 128);   // (8, 72)

    // split inputs (hi+lo — A operands)
    {
        int n4 = (int)((size_t)M_BIG * E_DIM / 4);
        split_f32<<<(n4 + 255) / 256, blk>>>((const float4*)x_feat, xf_h, xf_l, n4);
    }
    {
        int n4 = (int)((size_t)M_SML * E_DIM / 4);
        split_f32<<<(n4 + 255) / 256, blk>>>((const float4*)x, x_h, x_l, n4);
    }
    // convert weights (hi only — B operands)
    {
        int n4 = (int)(WSLOT / 4);
        int g = (n4 + 255) / 256;
        cvt_f32_hi<<<g, blk>>>((const float4*)w_q,  w_h + 0 * WSLOT, n4);
        cvt_f32_hi<<<g, blk>>>((const float4*)w_k1, w_h + 1 * WSLOT, n4);
        cvt_f32_hi<<<g, blk>>>((const float4*)w_k2, w_h + 2 * WSLOT, n4);
        cvt_f32_hi<<<g, blk>>>((const float4*)w_v1, w_h + 3 * WSLOT, n4);
        cvt_f32_hi<<<g, blk>>>((const float4*)w_v2, w_h + 4 * WSLOT, n4);
        cvt_f32_hi<<<3 * g, blk>>>((const float4*)in_w, w_h + 5 * WSLOT, 3 * n4);
        cvt_f32_hi<<<g, blk>>>((const float4*)out_w, w_h + 8 * WSLOT, n4);
    }

    // key path
    gemm_f16x2<2><<<gridBig, blk, GEMM_SMEM>>>(xf_h, xf_l, w_h + 1 * WSLOT,
                                               b_k1, nullptr, tmp_h, tmp_l);
    gemm_f16x2<1><<<gridBig, blk, GEMM_SMEM>>>(tmp_h, tmp_l, w_h + 2 * WSLOT,
                                               b_k2, key, nullptr, nullptr);
    ln_split<<<M_BIG, blk>>>(key, kn_h, kn_l, ln_k_w, ln_k_b);
    // value path
    gemm_f16x2<2><<<gridBig, blk, GEMM_SMEM>>>(xf_h, xf_l, w_h + 3 * WSLOT,
                                               b_v1, nullptr, tmp_h, tmp_l);
    gemm_f16x2<1><<<gridBig, blk, GEMM_SMEM>>>(tmp_h, tmp_l, w_h + 4 * WSLOT,
                                               b_v2, val, nullptr, nullptr);
    ln_split<<<M_BIG, blk>>>(val, vn_h, vn_l, ln_v_w, ln_v_b);
    // query path
    gemm_f16x2<0><<<gridSml, blk, GEMM_SMEM>>>(x_h, x_l, w_h + 0 * WSLOT,
                                               nullptr, qry, nullptr, nullptr);
    ln_split<<<M_SML, blk>>>(qry, qn_h, qn_l, ln_q_w, ln_q_b);
    // in-proj q/k/v
    gemm_f16x2<1><<<gridSml, blk, GEMM_SMEM>>>(qn_h, qn_l, w_h + 5 * WSLOT,
                                               in_b, qh, nullptr, nullptr);
    gemm_f16x2<1><<<gridBig, blk, GEMM_SMEM>>>(kn_h, kn_l, w_h + 6 * WSLOT,
                                               in_b + E_DIM, kh, nullptr, nullptr);
    gemm_f16x2<1><<<gridBig, blk, GEMM_SMEM>>>(vn_h, vn_l, w_h + 7 * WSLOT,
                                               in_b + 2 * E_DIM, vh, nullptr, nullptr);
    // attention
    attn_split<<<M_SML, blk>>>(qh, kh, vh, at_h, at_l);
    // out-proj -> d_out
    gemm_f16x2<1><<<gridSml, blk, GEMM_SMEM>>>(at_h, at_l, w_h + 8 * WSLOT,
                                               out_b, out, nullptr, nullptr);
}

// round 6
// speedup vs baseline: 2.9793x; 1.0725x over previous
#include <cuda_runtime.h>
#include <cuda_fp16.h>
#include <cstdint>
#include <cstddef>

// ---------------------------------------------------------------------------
// TokenPacker round 6: 2-term fp16 split GEMM, BK=64 (16 k-iters), 2-stage
// cp.async.cg pipeline, ldmatrix fragments, batched weight conversion.
// ---------------------------------------------------------------------------

#define E_DIM 1024
#define NQ 144
#define TN 576
#define NB 64
#define M_BIG  (NB * TN)   // 36864
#define M_SML  (NB * NQ)   // 9216

#define WSLOT ((size_t)E_DIM * E_DIM)

// fp16 hi/lo activation planes
__device__ __half g_xf_h [(size_t)M_BIG * E_DIM];
__device__ __half g_xf_l [(size_t)M_BIG * E_DIM];
__device__ __half g_x_h  [(size_t)M_SML * E_DIM];
__device__ __half g_x_l  [(size_t)M_SML * E_DIM];
__device__ __half g_tmp_h[(size_t)M_BIG * E_DIM];
__device__ __half g_tmp_l[(size_t)M_BIG * E_DIM];
__device__ __half g_kn_h [(size_t)M_BIG * E_DIM];
__device__ __half g_kn_l [(size_t)M_BIG * E_DIM];
__device__ __half g_vn_h [(size_t)M_BIG * E_DIM];
__device__ __half g_vn_l [(size_t)M_BIG * E_DIM];
__device__ __half g_qn_h [(size_t)M_SML * E_DIM];
__device__ __half g_qn_l [(size_t)M_SML * E_DIM];
__device__ __half g_at_h [(size_t)M_SML * E_DIM];
__device__ __half g_at_l [(size_t)M_SML * E_DIM];
// fp16 weight slots (hi only): 0=wq 1=wk1 2=wk2 3=wv1 4=wv2 5,6,7=in_w 8=out_w
__device__ __half g_w_h[9 * WSLOT];
// fp32 scratch
__device__ float g_key[(size_t)M_BIG * E_DIM];
__device__ float g_val[(size_t)M_BIG * E_DIM];
__device__ float g_qry[(size_t)M_SML * E_DIM];
__device__ float g_qh [(size_t)M_SML * E_DIM];
__device__ float g_kh [(size_t)M_BIG * E_DIM];
__device__ float g_vh [(size_t)M_BIG * E_DIM];

// ---------------------------------------------------------------------------
// helpers
// ---------------------------------------------------------------------------
__device__ __forceinline__ void mma16(float* c, const uint32_t* a, const uint32_t* b) {
    asm volatile(
        "mma.sync.aligned.m16n8k16.row.col.f32.f16.f16.f32 "
        "{%0,%1,%2,%3}, {%4,%5,%6,%7}, {%8,%9}, {%0,%1,%2,%3};\n"
        : "+f"(c[0]), "+f"(c[1]), "+f"(c[2]), "+f"(c[3])
        : "r"(a[0]), "r"(a[1]), "r"(a[2]), "r"(a[3]), "r"(b[0]), "r"(b[1]));
}

__device__ __forceinline__ void ldsm_x4(uint32_t* r, uint32_t addr) {
    asm volatile("ldmatrix.sync.aligned.m8n8.x4.shared.b16 {%0,%1,%2,%3}, [%4];"
        : "=r"(r[0]), "=r"(r[1]), "=r"(r[2]), "=r"(r[3]) : "r"(addr));
}

__device__ __forceinline__ void cp_async16(uint32_t saddr, const void* gmem) {
    asm volatile("cp.async.cg.shared.global [%0], [%1], 16;\n" :: "r"(saddr), "l"(gmem));
}
__device__ __forceinline__ void cp_commit() { asm volatile("cp.async.commit_group;\n"); }
template <int N>
__device__ __forceinline__ void cp_wait() { asm volatile("cp.async.wait_group %0;\n" :: "n"(N)); }

__device__ __forceinline__ void split_store2(__half* __restrict__ hi, __half* __restrict__ lo,
                                             size_t off, float a, float b) {
    __half h0 = __float2half_rn(a), h1 = __float2half_rn(b);
    __half l0 = __float2half_rn(a - __half2float(h0));
    __half l1 = __float2half_rn(b - __half2float(h1));
    *(__half2*)(hi + off) = __halves2half2(h0, h1);
    *(__half2*)(lo + off) = __halves2half2(l0, l1);
}

__device__ __forceinline__ float gelu_exact(float x) {
    return 0.5f * x * (1.0f + erff(x * 0.7071067811865476f));
}

// ---------------------------------------------------------------------------
// split kernels
// ---------------------------------------------------------------------------
__global__ __launch_bounds__(256)
void split_f32(const float4* __restrict__ src, __half* __restrict__ hi,
               __half* __restrict__ lo, int n4)
{
    int i = blockIdx.x * blockDim.x + threadIdx.x;
    if (i < n4) {
        float4 v = src[i];
        size_t off = (size_t)i * 4;
        split_store2(hi, lo, off,     v.x, v.y);
        split_store2(hi, lo, off + 2, v.z, v.w);
    }
}

struct WPtrs { const float4* s[9]; };

// batched weight conversion: blockIdx.y selects 1M-element slot
__global__ __launch_bounds__(256)
void cvt_weights(WPtrs p, __half* __restrict__ w_h)
{
    const int slot = blockIdx.y;
    const float4* src = p.s[slot];
    __half* dst = w_h + (size_t)slot * WSLOT;
    int i = blockIdx.x * blockDim.x + threadIdx.x;   // n4 = WSLOT/4 = 262144
    float4 v = src[i];
    __half2 a = __halves2half2(__float2half_rn(v.x), __float2half_rn(v.y));
    __half2 b = __halves2half2(__float2half_rn(v.z), __float2half_rn(v.w));
    *(__half2*)(dst + (size_t)i * 4)     = a;
    *(__half2*)(dst + (size_t)i * 4 + 2) = b;
}

// ---------------------------------------------------------------------------
// GEMM: C[M,1024] = (Ah+Al)[M,1024] @ Bh^T, 2 mma terms, ldmatrix.
// BK=64, 2-stage cp.async pipeline, BM=BN=128, 256 thr, warp tile 32x64.
// MODE 0: fp32 out. MODE 1: fp32 + bias. MODE 2: gelu(+bias) -> hi/lo planes.
// ---------------------------------------------------------------------------
#define BK 64
#define S16 72                        // halves per smem row (64 + 8 pad) = 144B
#define PLANE_B (128 * S16 * 2)       // 18432 bytes per plane
#define STAGE_B (3 * PLANE_B)         // 55296 bytes per stage (Ah, Al, Bh)
#define GEMM_SMEM (2 * STAGE_B)       // 110592 bytes
#define NKT (E_DIM / BK)              // 16

template<int MODE>
__global__ __launch_bounds__(256, 2)
void gemm_f16x2(const __half* __restrict__ Ah, const __half* __restrict__ Al,
                const __half* __restrict__ Bh,
                const float* __restrict__ bias,
                float* __restrict__ Cf,
                __half* __restrict__ Chi, __half* __restrict__ Clo)
{
    extern __shared__ __align__(128) char smraw[];
    const uint32_t smem_base = (uint32_t)__cvta_generic_to_shared(smraw);
    const int tid  = threadIdx.x;
    const int lane = tid & 31;
    const int wid  = tid >> 5;
    const int wm   = (wid >> 1) * 32;   // warp M offset
    const int wn   = (wid & 1) * 64;    // warp N offset
    const int bm   = blockIdx.y;
    const int bn   = blockIdx.x;

    float acc[2][8][4];
    #pragma unroll
    for (int mt = 0; mt < 2; mt++)
        #pragma unroll
        for (int nt = 0; nt < 8; nt++)
            #pragma unroll
            for (int i = 0; i < 4; i++) acc[mt][nt][i] = 0.0f;

    // ldmatrix per-lane byte offsets (within a plane), loop-invariant
    uint32_t aoff[2], boff[4];
    #pragma unroll
    for (int mt = 0; mt < 2; mt++)
        aoff[mt] = ((wm + mt * 16 + (lane & 15)) * S16 + ((lane >> 4) << 3)) * 2;
    #pragma unroll
    for (int j = 0; j < 4; j++)
        boff[j] = ((wn + (2 * j + ((lane >> 4) & 1)) * 8 + (lane & 7)) * S16
                   + (((lane >> 3) & 1) << 3)) * 2;

    // tile loader: 3 planes x 128 rows x 8 chunks(16B) = 3072 chunks, 12/thread
    auto load_tiles = [&](int kt, int stg) {
        const int k0 = kt * BK;
        const uint32_t base = smem_base + stg * STAGE_B;
        #pragma unroll
        for (int t = 0; t < 8; t++) {           // planes 0,1 (Ah, Al): 2048 chunks
            int idx = tid + t * 256;
            int plane = idx >> 10;
            int rem = idx & 1023;
            int row = rem >> 3, c = rem & 7;
            const __half* src = (plane ? Al : Ah)
                              + (size_t)(bm * 128 + row) * E_DIM + k0 + c * 8;
            cp_async16(base + plane * PLANE_B + row * (S16 * 2) + c * 16, src);
        }
        #pragma unroll
        for (int t = 0; t < 4; t++) {           // plane 2 (Bh): 1024 chunks
            int idx = tid + t * 256;
            int row = idx >> 3, c = idx & 7;
            const __half* src = Bh + (size_t)(bn * 128 + row) * E_DIM + k0 + c * 8;
            cp_async16(base + 2 * PLANE_B + row * (S16 * 2) + c * 16, src);
        }
    };

    load_tiles(0, 0); cp_commit();
    load_tiles(1, 1); cp_commit();

    for (int kt = 0; kt < NKT; kt++) {
        cp_wait<1>();            // stage kt&1 resident (next load may still fly)
        __syncthreads();

        const uint32_t sA  = smem_base + (kt & 1) * STAGE_B;
        const uint32_t sAl = sA + PLANE_B;
        const uint32_t sB  = sA + 2 * PLANE_B;

        #pragma unroll
        for (int ks = 0; ks < 4; ks++) {
            const uint32_t kbb = ks * 32;       // 16 halves = 32 bytes per half-step
            uint32_t ah0[4], ah1[4], al0[4], al1[4];
            ldsm_x4(ah0, sA  + aoff[0] + kbb);
            ldsm_x4(ah1, sA  + aoff[1] + kbb);
            ldsm_x4(al0, sAl + aoff[0] + kbb);
            ldsm_x4(al1, sAl + aoff[1] + kbb);
            uint32_t bb[4][4];
            #pragma unroll
            for (int j = 0; j < 4; j++)
                ldsm_x4(bb[j], sB + boff[j] + kbb);
            #pragma unroll
            for (int nt = 0; nt < 8; nt++) {
                const uint32_t* bp = &bb[nt >> 1][(nt & 1) * 2];
                mma16(acc[0][nt], ah0, bp);
                mma16(acc[0][nt], al0, bp);
                mma16(acc[1][nt], ah1, bp);
                mma16(acc[1][nt], al1, bp);
            }
        }
        __syncthreads();         // all warps done reading stage kt&1
        if (kt + 2 < NKT) load_tiles(kt + 2, kt & 1);
        cp_commit();             // (possibly empty group keeps counts aligned)
    }

    // epilogue
    #pragma unroll
    for (int mt = 0; mt < 2; mt++) {
        #pragma unroll
        for (int nt = 0; nt < 8; nt++) {
            int row0 = bm * 128 + wm + mt * 16 + (lane >> 2);
            int col  = bn * 128 + wn + nt * 8 + ((lane & 3) << 1);
            float bv0 = 0.0f, bv1 = 0.0f;
            if (MODE != 0) { bv0 = bias[col]; bv1 = bias[col + 1]; }
            float c0 = acc[mt][nt][0] + bv0;
            float c1 = acc[mt][nt][1] + bv1;
            float c2 = acc[mt][nt][2] + bv0;
            float c3 = acc[mt][nt][3] + bv1;
            if (MODE == 2) {
                c0 = gelu_exact(c0); c1 = gelu_exact(c1);
                c2 = gelu_exact(c2); c3 = gelu_exact(c3);
                size_t o0 = (size_t)row0 * E_DIM + col;
                size_t o1 = (size_t)(row0 + 8) * E_DIM + col;
                split_store2(Chi, Clo, o0, c0, c1);
                split_store2(Chi, Clo, o1, c2, c3);
            } else {
                *(float2*)(Cf + (size_t)row0 * E_DIM + col)       = make_float2(c0, c1);
                *(float2*)(Cf + (size_t)(row0 + 8) * E_DIM + col) = make_float2(c2, c3);
            }
        }
    }
}

// ---------------------------------------------------------------------------
// LayerNorm over last dim (1024) -> fp16 hi/lo planes. 256 thr per row.
// ---------------------------------------------------------------------------
__global__ __launch_bounds__(256)
void ln_split(const float* __restrict__ X, __half* __restrict__ Hi, __half* __restrict__ Lo,
              const float* __restrict__ w, const float* __restrict__ b)
{
    const size_t row = blockIdx.x;
    const float4* xp = (const float4*)(X + row * E_DIM);
    const int tid  = threadIdx.x;
    const int lane = tid & 31;
    const int wid  = tid >> 5;

    float4 v = xp[tid];
    float s  = v.x + v.y + v.z + v.w;
    float ss = v.x * v.x + v.y * v.y + v.z * v.z + v.w * v.w;
    #pragma unroll
    for (int off = 16; off; off >>= 1) {
        s  += __shfl_xor_sync(0xffffffffu, s, off);
        ss += __shfl_xor_sync(0xffffffffu, ss, off);
    }
    __shared__ float rs[8], rss[8];
    if (lane == 0) { rs[wid] = s; rss[wid] = ss; }
    __syncthreads();
    float ts = 0.0f, tss = 0.0f;
    #pragma unroll
    for (int i = 0; i < 8; i++) { ts += rs[i]; tss += rss[i]; }
    const float mean = ts * (1.0f / 1024.0f);
    const float var  = tss * (1.0f / 1024.0f) - mean * mean;
    const float inv  = rsqrtf(var + 1e-6f);

    const float4 w4 = ((const float4*)w)[tid];
    const float4 b4 = ((const float4*)b)[tid];
    float y0 = (v.x - mean) * inv * w4.x + b4.x;
    float y1 = (v.y - mean) * inv * w4.y + b4.y;
    float y2 = (v.z - mean) * inv * w4.z + b4.z;
    float y3 = (v.w - mean) * inv * w4.w + b4.w;
    size_t off = row * E_DIM + (size_t)tid * 4;
    split_store2(Hi, Lo, off,     y0, y1);
    split_store2(Hi, Lo, off + 2, y2, y3);
}

// ---------------------------------------------------------------------------
// Attention: per (n, q): 8 heads x (1 query, 4 keys); output -> hi/lo planes.
// ---------------------------------------------------------------------------
__global__ __launch_bounds__(256)
void attn_split(const float* __restrict__ qh, const float* __restrict__ kh,
                const float* __restrict__ vh, __half* __restrict__ Ohi,
                __half* __restrict__ Olo)
{
    const int bq   = blockIdx.x;
    const int n    = bq / NQ;
    const int q    = bq - n * NQ;
    const int h    = threadIdx.x >> 5;
    const int lane = threadIdx.x & 31;
    const int qr   = q / 12;
    const int qc   = q - qr * 12;

    const size_t qoff = (size_t)bq * E_DIM + h * 128 + lane * 4;
    const float4 qv = *(const float4*)(qh + qoff);

    float s[4];
    float4 vv[4];
    #pragma unroll
    for (int kk = 0; kk < 4; kk++) {
        const int t = (qr * 2 + (kk >> 1)) * 24 + qc * 2 + (kk & 1);
        const size_t krow = (size_t)(n * TN + t) * E_DIM + h * 128 + lane * 4;
        const float4 k4 = *(const float4*)(kh + krow);
        vv[kk] = *(const float4*)(vh + krow);
        float d = qv.x * k4.x + qv.y * k4.y + qv.z * k4.z + qv.w * k4.w;
        #pragma unroll
        for (int off = 16; off; off >>= 1) d += __shfl_xor_sync(0xffffffffu, d, off);
        s[kk] = d * 0.08838834764831845f;
    }
    const float m = fmaxf(fmaxf(s[0], s[1]), fmaxf(s[2], s[3]));
    float p[4], sum = 0.0f;
    #pragma unroll
    for (int kk = 0; kk < 4; kk++) { p[kk] = expf(s[kk] - m); sum += p[kk]; }
    const float inv = 1.0f / sum;
    float4 o = make_float4(0.f, 0.f, 0.f, 0.f);
    #pragma unroll
    for (int kk = 0; kk < 4; kk++) {
        const float pk = p[kk] * inv;
        o.x += pk * vv[kk].x; o.y += pk * vv[kk].y;
        o.z += pk * vv[kk].z; o.w += pk * vv[kk].w;
    }
    split_store2(Ohi, Olo, qoff,     o.x, o.y);
    split_store2(Ohi, Olo, qoff + 2, o.z, o.w);
}

// ---------------------------------------------------------------------------
// launch
// ---------------------------------------------------------------------------
extern "C" void kernel_launch(void* const* d_in, const int* in_sizes, int n_in,
                              void* d_out, int out_size)
{
    const float* x      = (const float*)d_in[0];
    const float* x_feat = (const float*)d_in[1];
    const float* w_q    = (const float*)d_in[2];
    const float* w_k1   = (const float*)d_in[3];
    const float* b_k1   = (const float*)d_in[4];
    const float* w_k2   = (const float*)d_in[5];
    const float* b_k2   = (const float*)d_in[6];
    const float* w_v1   = (const float*)d_in[7];
    const float* b_v1   = (const float*)d_in[8];
    const float* w_v2   = (const float*)d_in[9];
    const float* b_v2   = (const float*)d_in[10];
    const float* ln_q_w = (const float*)d_in[11];
    const float* ln_q_b = (const float*)d_in[12];
    const float* ln_k_w = (const float*)d_in[13];
    const float* ln_k_b = (const float*)d_in[14];
    const float* ln_v_w = (const float*)d_in[15];
    const float* ln_v_b = (const float*)d_in[16];
    const float* in_w   = (const float*)d_in[17];
    const float* in_b   = (const float*)d_in[18];
    const float* out_w  = (const float*)d_in[19];
    const float* out_b  = (const float*)d_in[20];
    float* out = (float*)d_out;

    __half *xf_h, *xf_l, *x_h, *x_l, *tmp_h, *tmp_l, *kn_h, *kn_l, *vn_h, *vn_l;
    __half *qn_h, *qn_l, *at_h, *at_l, *w_h;
    float *key, *val, *qry, *qh, *kh, *vh;
    cudaGetSymbolAddress((void**)&xf_h, g_xf_h);  cudaGetSymbolAddress((void**)&xf_l, g_xf_l);
    cudaGetSymbolAddress((void**)&x_h,  g_x_h);   cudaGetSymbolAddress((void**)&x_l,  g_x_l);
    cudaGetSymbolAddress((void**)&tmp_h,g_tmp_h); cudaGetSymbolAddress((void**)&tmp_l,g_tmp_l);
    cudaGetSymbolAddress((void**)&kn_h, g_kn_h);  cudaGetSymbolAddress((void**)&kn_l, g_kn_l);
    cudaGetSymbolAddress((void**)&vn_h, g_vn_h);  cudaGetSymbolAddress((void**)&vn_l, g_vn_l);
    cudaGetSymbolAddress((void**)&qn_h, g_qn_h);  cudaGetSymbolAddress((void**)&qn_l, g_qn_l);
    cudaGetSymbolAddress((void**)&at_h, g_at_h);  cudaGetSymbolAddress((void**)&at_l, g_at_l);
    cudaGetSymbolAddress((void**)&w_h,  g_w_h);
    cudaGetSymbolAddress((void**)&key,  g_key);   cudaGetSymbolAddress((void**)&val,  g_val);
    cudaGetSymbolAddress((void**)&qry,  g_qry);   cudaGetSymbolAddress((void**)&qh,   g_qh);
    cudaGetSymbolAddress((void**)&kh,   g_kh);    cudaGetSymbolAddress((void**)&vh,   g_vh);

    cudaFuncSetAttribute(gemm_f16x2<0>, cudaFuncAttributeMaxDynamicSharedMemorySize, GEMM_SMEM);
    cudaFuncSetAttribute(gemm_f16x2<1>, cudaFuncAttributeMaxDynamicSharedMemorySize, GEMM_SMEM);
    cudaFuncSetAttribute(gemm_f16x2<2>, cudaFuncAttributeMaxDynamicSharedMemorySize, GEMM_SMEM);

    dim3 blk(256);
    dim3 gridBig(E_DIM / 128, M_BIG / 128);   // (8, 288)
    dim3 gridSml(E_DIM / 128, M_SML / 128);   // (8, 72)

    // split inputs (hi+lo — A operands)
    {
        int n4 = (int)((size_t)M_BIG * E_DIM / 4);
        split_f32<<<(n4 + 255) / 256, blk>>>((const float4*)x_feat, xf_h, xf_l, n4);
    }
    {
        int n4 = (int)((size_t)M_SML * E_DIM / 4);
        split_f32<<<(n4 + 255) / 256, blk>>>((const float4*)x, x_h, x_l, n4);
    }
    // convert all 9 weight slots in one launch (hi only — B operands)
    {
        WPtrs p;
        p.s[0] = (const float4*)w_q;
        p.s[1] = (const float4*)w_k1;
        p.s[2] = (const float4*)w_k2;
        p.s[3] = (const float4*)w_v1;
        p.s[4] = (const float4*)w_v2;
        p.s[5] = (const float4*)in_w;
        p.s[6] = (const float4*)(in_w + WSLOT);
        p.s[7] = (const float4*)(in_w + 2 * WSLOT);
        p.s[8] = (const float4*)out_w;
        dim3 g((int)(WSLOT / 4 / 256), 9);
        cvt_weights<<<g, blk>>>(p, w_h);
    }

    // key path
    gemm_f16x2<2><<<gridBig, blk, GEMM_SMEM>>>(xf_h, xf_l, w_h + 1 * WSLOT,
                                               b_k1, nullptr, tmp_h, tmp_l);
    gemm_f16x2<1><<<gridBig, blk, GEMM_SMEM>>>(tmp_h, tmp_l, w_h + 2 * WSLOT,
                                               b_k2, key, nullptr, nullptr);
    ln_split<<<M_BIG, blk>>>(key, kn_h, kn_l, ln_k_w, ln_k_b);
    // value path
    gemm_f16x2<2><<<gridBig, blk, GEMM_SMEM>>>(xf_h, xf_l, w_h + 3 * WSLOT,
                                               b_v1, nullptr, tmp_h, tmp_l);
    gemm_f16x2<1><<<gridBig, blk, GEMM_SMEM>>>(tmp_h, tmp_l, w_h + 4 * WSLOT,
                                               b_v2, val, nullptr, nullptr);
    ln_split<<<M_BIG, blk>>>(val, vn_h, vn_l, ln_v_w, ln_v_b);
    // query path
    gemm_f16x2<0><<<gridSml, blk, GEMM_SMEM>>>(x_h, x_l, w_h + 0 * WSLOT,
                                               nullptr, qry, nullptr, nullptr);
    ln_split<<<M_SML, blk>>>(qry, qn_h, qn_l, ln_q_w, ln_q_b);
    // in-proj q/k/v
    gemm_f16x2<1><<<gridSml, blk, GEMM_SMEM>>>(qn_h, qn_l, w_h + 5 * WSLOT,
                                               in_b, qh, nullptr, nullptr);
    gemm_f16x2<1><<<gridBig, blk, GEMM_SMEM>>>(kn_h, kn_l, w_h + 6 * WSLOT,
                                               in_b + E_DIM, kh, nullptr, nullptr);
    gemm_f16x2<1><<<gridBig, blk, GEMM_SMEM>>>(vn_h, vn_l, w_h + 7 * WSLOT,
                                               in_b + 2 * E_DIM, vh, nullptr, nullptr);
    // attention
    attn_split<<<M_SML, blk>>>(qh, kh, vh, at_h, at_l);
    // out-proj -> d_out
    gemm_f16x2<1><<<gridSml, blk, GEMM_SMEM>>>(at_h, at_l, w_h + 8 * WSLOT,
                                               out_b, out, nullptr, nullptr);
}

// round 7
// speedup vs baseline: 3.0022x; 1.0077x over previous
#include <cuda_runtime.h>
#include <cuda_fp16.h>
#include <cstdint>
#include <cstddef>

// ---------------------------------------------------------------------------
// TokenPacker round 7: same as round 6 (2-term fp16 split, BK=64, 2-stage
// cp.async.cg, ldmatrix) but mma issue order restructured: four independent
// 8-mma sweeps per half-step so same-accumulator RAW distance is 16, and the
// mma asm is non-volatile so the scheduler may interleave further.
// ---------------------------------------------------------------------------

#define E_DIM 1024
#define NQ 144
#define TN 576
#define NB 64
#define M_BIG  (NB * TN)   // 36864
#define M_SML  (NB * NQ)   // 9216

#define WSLOT ((size_t)E_DIM * E_DIM)

// fp16 hi/lo activation planes
__device__ __half g_xf_h [(size_t)M_BIG * E_DIM];
__device__ __half g_xf_l [(size_t)M_BIG * E_DIM];
__device__ __half g_x_h  [(size_t)M_SML * E_DIM];
__device__ __half g_x_l  [(size_t)M_SML * E_DIM];
__device__ __half g_tmp_h[(size_t)M_BIG * E_DIM];
__device__ __half g_tmp_l[(size_t)M_BIG * E_DIM];
__device__ __half g_kn_h [(size_t)M_BIG * E_DIM];
__device__ __half g_kn_l [(size_t)M_BIG * E_DIM];
__device__ __half g_vn_h [(size_t)M_BIG * E_DIM];
__device__ __half g_vn_l [(size_t)M_BIG * E_DIM];
__device__ __half g_qn_h [(size_t)M_SML * E_DIM];
__device__ __half g_qn_l [(size_t)M_SML * E_DIM];
__device__ __half g_at_h [(size_t)M_SML * E_DIM];
__device__ __half g_at_l [(size_t)M_SML * E_DIM];
// fp16 weight slots (hi only): 0=wq 1=wk1 2=wk2 3=wv1 4=wv2 5,6,7=in_w 8=out_w
__device__ __half g_w_h[9 * WSLOT];
// fp32 scratch
__device__ float g_key[(size_t)M_BIG * E_DIM];
__device__ float g_val[(size_t)M_BIG * E_DIM];
__device__ float g_qry[(size_t)M_SML * E_DIM];
__device__ float g_qh [(size_t)M_SML * E_DIM];
__device__ float g_kh [(size_t)M_BIG * E_DIM];
__device__ float g_vh [(size_t)M_BIG * E_DIM];

// ---------------------------------------------------------------------------
// helpers
// ---------------------------------------------------------------------------
__device__ __forceinline__ void mma16(float* c, const uint32_t* a, const uint32_t* b) {
    // NOT volatile: pure register op; let the scheduler interleave.
    asm("mma.sync.aligned.m16n8k16.row.col.f32.f16.f16.f32 "
        "{%0,%1,%2,%3}, {%4,%5,%6,%7}, {%8,%9}, {%0,%1,%2,%3};\n"
        : "+f"(c[0]), "+f"(c[1]), "+f"(c[2]), "+f"(c[3])
        : "r"(a[0]), "r"(a[1]), "r"(a[2]), "r"(a[3]), "r"(b[0]), "r"(b[1]));
}

__device__ __forceinline__ void ldsm_x4(uint32_t* r, uint32_t addr) {
    asm volatile("ldmatrix.sync.aligned.m8n8.x4.shared.b16 {%0,%1,%2,%3}, [%4];"
        : "=r"(r[0]), "=r"(r[1]), "=r"(r[2]), "=r"(r[3]) : "r"(addr));
}

__device__ __forceinline__ void cp_async16(uint32_t saddr, const void* gmem) {
    asm volatile("cp.async.cg.shared.global [%0], [%1], 16;\n" :: "r"(saddr), "l"(gmem));
}
__device__ __forceinline__ void cp_commit() { asm volatile("cp.async.commit_group;\n"); }
template <int N>
__device__ __forceinline__ void cp_wait() { asm volatile("cp.async.wait_group %0;\n" :: "n"(N)); }

__device__ __forceinline__ void split_store2(__half* __restrict__ hi, __half* __restrict__ lo,
                                             size_t off, float a, float b) {
    __half h0 = __float2half_rn(a), h1 = __float2half_rn(b);
    __half l0 = __float2half_rn(a - __half2float(h0));
    __half l1 = __float2half_rn(b - __half2float(h1));
    *(__half2*)(hi + off) = __halves2half2(h0, h1);
    *(__half2*)(lo + off) = __halves2half2(l0, l1);
}

__device__ __forceinline__ float gelu_exact(float x) {
    return 0.5f * x * (1.0f + erff(x * 0.7071067811865476f));
}

// ---------------------------------------------------------------------------
// split kernels
// ---------------------------------------------------------------------------
__global__ __launch_bounds__(256)
void split_f32(const float4* __restrict__ src, __half* __restrict__ hi,
               __half* __restrict__ lo, int n4)
{
    int i = blockIdx.x * blockDim.x + threadIdx.x;
    if (i < n4) {
        float4 v = src[i];
        size_t off = (size_t)i * 4;
        split_store2(hi, lo, off,     v.x, v.y);
        split_store2(hi, lo, off + 2, v.z, v.w);
    }
}

struct WPtrs { const float4* s[9]; };

__global__ __launch_bounds__(256)
void cvt_weights(WPtrs p, __half* __restrict__ w_h)
{
    const int slot = blockIdx.y;
    const float4* src = p.s[slot];
    __half* dst = w_h + (size_t)slot * WSLOT;
    int i = blockIdx.x * blockDim.x + threadIdx.x;
    float4 v = src[i];
    __half2 a = __halves2half2(__float2half_rn(v.x), __float2half_rn(v.y));
    __half2 b = __halves2half2(__float2half_rn(v.z), __float2half_rn(v.w));
    *(__half2*)(dst + (size_t)i * 4)     = a;
    *(__half2*)(dst + (size_t)i * 4 + 2) = b;
}

// ---------------------------------------------------------------------------
// GEMM: C[M,1024] = (Ah+Al)[M,1024] @ Bh^T, 2 mma terms, ldmatrix.
// BK=64, 2-stage cp.async pipeline, BM=BN=128, 256 thr, warp tile 32x64.
// MODE 0: fp32 out. MODE 1: fp32 + bias. MODE 2: gelu(+bias) -> hi/lo planes.
// ---------------------------------------------------------------------------
#define BK 64
#define S16 72                        // halves per smem row (64 + 8 pad) = 144B
#define PLANE_B (128 * S16 * 2)       // 18432 bytes per plane
#define STAGE_B (3 * PLANE_B)         // 55296 bytes per stage (Ah, Al, Bh)
#define GEMM_SMEM (2 * STAGE_B)       // 110592 bytes
#define NKT (E_DIM / BK)              // 16

template<int MODE>
__global__ __launch_bounds__(256, 2)
void gemm_f16x2(const __half* __restrict__ Ah, const __half* __restrict__ Al,
                const __half* __restrict__ Bh,
                const float* __restrict__ bias,
                float* __restrict__ Cf,
                __half* __restrict__ Chi, __half* __restrict__ Clo)
{
    extern __shared__ __align__(128) char smraw[];
    const uint32_t smem_base = (uint32_t)__cvta_generic_to_shared(smraw);
    const int tid  = threadIdx.x;
    const int lane = tid & 31;
    const int wid  = tid >> 5;
    const int wm   = (wid >> 1) * 32;   // warp M offset
    const int wn   = (wid & 1) * 64;    // warp N offset
    const int bm   = blockIdx.y;
    const int bn   = blockIdx.x;

    float acc[2][8][4];
    #pragma unroll
    for (int mt = 0; mt < 2; mt++)
        #pragma unroll
        for (int nt = 0; nt < 8; nt++)
            #pragma unroll
            for (int i = 0; i < 4; i++) acc[mt][nt][i] = 0.0f;

    // ldmatrix per-lane byte offsets (within a plane), loop-invariant
    uint32_t aoff[2], boff[4];
    #pragma unroll
    for (int mt = 0; mt < 2; mt++)
        aoff[mt] = ((wm + mt * 16 + (lane & 15)) * S16 + ((lane >> 4) << 3)) * 2;
    #pragma unroll
    for (int j = 0; j < 4; j++)
        boff[j] = ((wn + (2 * j + ((lane >> 4) & 1)) * 8 + (lane & 7)) * S16
                   + (((lane >> 3) & 1) << 3)) * 2;

    // tile loader: 3 planes x 128 rows x 8 chunks(16B) = 3072 chunks, 12/thread
    auto load_tiles = [&](int kt, int stg) {
        const int k0 = kt * BK;
        const uint32_t base = smem_base + stg * STAGE_B;
        #pragma unroll
        for (int t = 0; t < 8; t++) {           // planes 0,1 (Ah, Al): 2048 chunks
            int idx = tid + t * 256;
            int plane = idx >> 10;
            int rem = idx & 1023;
            int row = rem >> 3, c = rem & 7;
            const __half* src = (plane ? Al : Ah)
                              + (size_t)(bm * 128 + row) * E_DIM + k0 + c * 8;
            cp_async16(base + plane * PLANE_B + row * (S16 * 2) + c * 16, src);
        }
        #pragma unroll
        for (int t = 0; t < 4; t++) {           // plane 2 (Bh): 1024 chunks
            int idx = tid + t * 256;
            int row = idx >> 3, c = idx & 7;
            const __half* src = Bh + (size_t)(bn * 128 + row) * E_DIM + k0 + c * 8;
            cp_async16(base + 2 * PLANE_B + row * (S16 * 2) + c * 16, src);
        }
    };

    load_tiles(0, 0); cp_commit();
    load_tiles(1, 1); cp_commit();

    for (int kt = 0; kt < NKT; kt++) {
        cp_wait<1>();            // stage kt&1 resident (next load may still fly)
        __syncthreads();

        const uint32_t sA  = smem_base + (kt & 1) * STAGE_B;
        const uint32_t sAl = sA + PLANE_B;
        const uint32_t sB  = sA + 2 * PLANE_B;

        #pragma unroll
        for (int ks = 0; ks < 4; ks++) {
            const uint32_t kbb = ks * 32;       // 16 halves = 32 bytes per half-step
            uint32_t ah0[4], ah1[4], al0[4], al1[4];
            ldsm_x4(ah0, sA  + aoff[0] + kbb);
            ldsm_x4(ah1, sA  + aoff[1] + kbb);
            ldsm_x4(al0, sAl + aoff[0] + kbb);
            ldsm_x4(al1, sAl + aoff[1] + kbb);
            uint32_t bb[4][4];
            #pragma unroll
            for (int j = 0; j < 4; j++)
                ldsm_x4(bb[j], sB + boff[j] + kbb);

            // four independent 8-mma sweeps: same-acc RAW distance = 16 mma
            #pragma unroll
            for (int nt = 0; nt < 8; nt++)
                mma16(acc[0][nt], ah0, &bb[nt >> 1][(nt & 1) * 2]);
            #pragma unroll
            for (int nt = 0; nt < 8; nt++)
                mma16(acc[1][nt], ah1, &bb[nt >> 1][(nt & 1) * 2]);
            #pragma unroll
            for (int nt = 0; nt < 8; nt++)
                mma16(acc[0][nt], al0, &bb[nt >> 1][(nt & 1) * 2]);
            #pragma unroll
            for (int nt = 0; nt < 8; nt++)
                mma16(acc[1][nt], al1, &bb[nt >> 1][(nt & 1) * 2]);
        }
        __syncthreads();         // all warps done reading stage kt&1
        if (kt + 2 < NKT) load_tiles(kt + 2, kt & 1);
        cp_commit();             // (possibly empty group keeps counts aligned)
    }

    // epilogue
    #pragma unroll
    for (int mt = 0; mt < 2; mt++) {
        #pragma unroll
        for (int nt = 0; nt < 8; nt++) {
            int row0 = bm * 128 + wm + mt * 16 + (lane >> 2);
            int col  = bn * 128 + wn + nt * 8 + ((lane & 3) << 1);
            float bv0 = 0.0f, bv1 = 0.0f;
            if (MODE != 0) { bv0 = bias[col]; bv1 = bias[col + 1]; }
            float c0 = acc[mt][nt][0] + bv0;
            float c1 = acc[mt][nt][1] + bv1;
            float c2 = acc[mt][nt][2] + bv0;
            float c3 = acc[mt][nt][3] + bv1;
            if (MODE == 2) {
                c0 = gelu_exact(c0); c1 = gelu_exact(c1);
                c2 = gelu_exact(c2); c3 = gelu_exact(c3);
                size_t o0 = (size_t)row0 * E_DIM + col;
                size_t o1 = (size_t)(row0 + 8) * E_DIM + col;
                split_store2(Chi, Clo, o0, c0, c1);
                split_store2(Chi, Clo, o1, c2, c3);
            } else {
                *(float2*)(Cf + (size_t)row0 * E_DIM + col)       = make_float2(c0, c1);
                *(float2*)(Cf + (size_t)(row0 + 8) * E_DIM + col) = make_float2(c2, c3);
            }
        }
    }
}

// ---------------------------------------------------------------------------
// LayerNorm over last dim (1024) -> fp16 hi/lo planes. 256 thr per row.
// ---------------------------------------------------------------------------
__global__ __launch_bounds__(256)
void ln_split(const float* __restrict__ X, __half* __restrict__ Hi, __half* __restrict__ Lo,
              const float* __restrict__ w, const float* __restrict__ b)
{
    const size_t row = blockIdx.x;
    const float4* xp = (const float4*)(X + row * E_DIM);
    const int tid  = threadIdx.x;
    const int lane = tid & 31;
    const int wid  = tid >> 5;

    float4 v = xp[tid];
    float s  = v.x + v.y + v.z + v.w;
    float ss = v.x * v.x + v.y * v.y + v.z * v.z + v.w * v.w;
    #pragma unroll
    for (int off = 16; off; off >>= 1) {
        s  += __shfl_xor_sync(0xffffffffu, s, off);
        ss += __shfl_xor_sync(0xffffffffu, ss, off);
    }
    __shared__ float rs[8], rss[8];
    if (lane == 0) { rs[wid] = s; rss[wid] = ss; }
    __syncthreads();
    float ts = 0.0f, tss = 0.0f;
    #pragma unroll
    for (int i = 0; i < 8; i++) { ts += rs[i]; tss += rss[i]; }
    const float mean = ts * (1.0f / 1024.0f);
    const float var  = tss * (1.0f / 1024.0f) - mean * mean;
    const float inv  = rsqrtf(var + 1e-6f);

    const float4 w4 = ((const float4*)w)[tid];
    const float4 b4 = ((const float4*)b)[tid];
    float y0 = (v.x - mean) * inv * w4.x + b4.x;
    float y1 = (v.y - mean) * inv * w4.y + b4.y;
    float y2 = (v.z - mean) * inv * w4.z + b4.z;
    float y3 = (v.w - mean) * inv * w4.w + b4.w;
    size_t off = row * E_DIM + (size_t)tid * 4;
    split_store2(Hi, Lo, off,     y0, y1);
    split_store2(Hi, Lo, off + 2, y2, y3);
}

// ---------------------------------------------------------------------------
// Attention: per (n, q): 8 heads x (1 query, 4 keys); output -> hi/lo planes.
// ---------------------------------------------------------------------------
__global__ __launch_bounds__(256)
void attn_split(const float* __restrict__ qh, const float* __restrict__ kh,
                const float* __restrict__ vh, __half* __restrict__ Ohi,
                __half* __restrict__ Olo)
{
    const int bq   = blockIdx.x;
    const int n    = bq / NQ;
    const int q    = bq - n * NQ;
    const int h    = threadIdx.x >> 5;
    const int lane = threadIdx.x & 31;
    const int qr   = q / 12;
    const int qc   = q - qr * 12;

    const size_t qoff = (size_t)bq * E_DIM + h * 128 + lane * 4;
    const float4 qv = *(const float4*)(qh + qoff);

    float s[4];
    float4 vv[4];
    #pragma unroll
    for (int kk = 0; kk < 4; kk++) {
        const int t = (qr * 2 + (kk >> 1)) * 24 + qc * 2 + (kk & 1);
        const size_t krow = (size_t)(n * TN + t) * E_DIM + h * 128 + lane * 4;
        const float4 k4 = *(const float4*)(kh + krow);
        vv[kk] = *(const float4*)(vh + krow);
        float d = qv.x * k4.x + qv.y * k4.y + qv.z * k4.z + qv.w * k4.w;
        #pragma unroll
        for (int off = 16; off; off >>= 1) d += __shfl_xor_sync(0xffffffffu, d, off);
        s[kk] = d * 0.08838834764831845f;
    }
    const float m = fmaxf(fmaxf(s[0], s[1]), fmaxf(s[2], s[3]));
    float p[4], sum = 0.0f;
    #pragma unroll
    for (int kk = 0; kk < 4; kk++) { p[kk] = expf(s[kk] - m); sum += p[kk]; }
    const float inv = 1.0f / sum;
    float4 o = make_float4(0.f, 0.f, 0.f, 0.f);
    #pragma unroll
    for (int kk = 0; kk < 4; kk++) {
        const float pk = p[kk] * inv;
        o.x += pk * vv[kk].x; o.y += pk * vv[kk].y;
        o.z += pk * vv[kk].z; o.w += pk * vv[kk].w;
    }
    split_store2(Ohi, Olo, qoff,     o.x, o.y);
    split_store2(Ohi, Olo, qoff + 2, o.z, o.w);
}

// ---------------------------------------------------------------------------
// launch
// ---------------------------------------------------------------------------
extern "C" void kernel_launch(void* const* d_in, const int* in_sizes, int n_in,
                              void* d_out, int out_size)
{
    const float* x      = (const float*)d_in[0];
    const float* x_feat = (const float*)d_in[1];
    const float* w_q    = (const float*)d_in[2];
    const float* w_k1   = (const float*)d_in[3];
    const float* b_k1   = (const float*)d_in[4];
    const float* w_k2   = (const float*)d_in[5];
    const float* b_k2   = (const float*)d_in[6];
    const float* w_v1   = (const float*)d_in[7];
    const float* b_v1   = (const float*)d_in[8];
    const float* w_v2   = (const float*)d_in[9];
    const float* b_v2   = (const float*)d_in[10];
    const float* ln_q_w = (const float*)d_in[11];
    const float* ln_q_b = (const float*)d_in[12];
    const float* ln_k_w = (const float*)d_in[13];
    const float* ln_k_b = (const float*)d_in[14];
    const float* ln_v_w = (const float*)d_in[15];
    const float* ln_v_b = (const float*)d_in[16];
    const float* in_w   = (const float*)d_in[17];
    const float* in_b   = (const float*)d_in[18];
    const float* out_w  = (const float*)d_in[19];
    const float* out_b  = (const float*)d_in[20];
    float* out = (float*)d_out;

    __half *xf_h, *xf_l, *x_h, *x_l, *tmp_h, *tmp_l, *kn_h, *kn_l, *vn_h, *vn_l;
    __half *qn_h, *qn_l, *at_h, *at_l, *w_h;
    float *key, *val, *qry, *qh, *kh, *vh;
    cudaGetSymbolAddress((void**)&xf_h, g_xf_h);  cudaGetSymbolAddress((void**)&xf_l, g_xf_l);
    cudaGetSymbolAddress((void**)&x_h,  g_x_h);   cudaGetSymbolAddress((void**)&x_l,  g_x_l);
    cudaGetSymbolAddress((void**)&tmp_h,g_tmp_h); cudaGetSymbolAddress((void**)&tmp_l,g_tmp_l);
    cudaGetSymbolAddress((void**)&kn_h, g_kn_h);  cudaGetSymbolAddress((void**)&kn_l, g_kn_l);
    cudaGetSymbolAddress((void**)&vn_h, g_vn_h);  cudaGetSymbolAddress((void**)&vn_l, g_vn_l);
    cudaGetSymbolAddress((void**)&qn_h, g_qn_h);  cudaGetSymbolAddress((void**)&qn_l, g_qn_l);
    cudaGetSymbolAddress((void**)&at_h, g_at_h);  cudaGetSymbolAddress((void**)&at_l, g_at_l);
    cudaGetSymbolAddress((void**)&w_h,  g_w_h);
    cudaGetSymbolAddress((void**)&key,  g_key);   cudaGetSymbolAddress((void**)&val,  g_val);
    cudaGetSymbolAddress((void**)&qry,  g_qry);   cudaGetSymbolAddress((void**)&qh,   g_qh);
    cudaGetSymbolAddress((void**)&kh,   g_kh);    cudaGetSymbolAddress((void**)&vh,   g_vh);

    cudaFuncSetAttribute(gemm_f16x2<0>, cudaFuncAttributeMaxDynamicSharedMemorySize, GEMM_SMEM);
    cudaFuncSetAttribute(gemm_f16x2<1>, cudaFuncAttributeMaxDynamicSharedMemorySize, GEMM_SMEM);
    cudaFuncSetAttribute(gemm_f16x2<2>, cudaFuncAttributeMaxDynamicSharedMemorySize, GEMM_SMEM);

    dim3 blk(256);
    dim3 gridBig(E_DIM / 128, M_BIG / 128);   // (8, 288)
    dim3 gridSml(E_DIM / 128, M_SML / 128);   // (8, 72)

    // split inputs (hi+lo — A operands)
    {
        int n4 = (int)((size_t)M_BIG * E_DIM / 4);
        split_f32<<<(n4 + 255) / 256, blk>>>((const float4*)x_feat, xf_h, xf_l, n4);
    }
    {
        int n4 = (int)((size_t)M_SML * E_DIM / 4);
        split_f32<<<(n4 + 255) / 256, blk>>>((const float4*)x, x_h, x_l, n4);
    }
    // convert all 9 weight slots in one launch (hi only — B operands)
    {
        WPtrs p;
        p.s[0] = (const float4*)w_q;
        p.s[1] = (const float4*)w_k1;
        p.s[2] = (const float4*)w_k2;
        p.s[3] = (const float4*)w_v1;
        p.s[4] = (const float4*)w_v2;
        p.s[5] = (const float4*)in_w;
        p.s[6] = (const float4*)(in_w + WSLOT);
        p.s[7] = (const float4*)(in_w + 2 * WSLOT);
        p.s[8] = (const float4*)out_w;
        dim3 g((int)(WSLOT / 4 / 256), 9);
        cvt_weights<<<g, blk>>>(p, w_h);
    }

    // key path
    gemm_f16x2<2><<<gridBig, blk, GEMM_SMEM>>>(xf_h, xf_l, w_h + 1 * WSLOT,
                                               b_k1, nullptr, tmp_h, tmp_l);
    gemm_f16x2<1><<<gridBig, blk, GEMM_SMEM>>>(tmp_h, tmp_l, w_h + 2 * WSLOT,
                                               b_k2, key, nullptr, nullptr);
    ln_split<<<M_BIG, blk>>>(key, kn_h, kn_l, ln_k_w, ln_k_b);
    // value path
    gemm_f16x2<2><<<gridBig, blk, GEMM_SMEM>>>(xf_h, xf_l, w_h + 3 * WSLOT,
                                               b_v1, nullptr, tmp_h, tmp_l);
    gemm_f16x2<1><<<gridBig, blk, GEMM_SMEM>>>(tmp_h, tmp_l, w_h + 4 * WSLOT,
                                               b_v2, val, nullptr, nullptr);
    ln_split<<<M_BIG, blk>>>(val, vn_h, vn_l, ln_v_w, ln_v_b);
    // query path
    gemm_f16x2<0><<<gridSml, blk, GEMM_SMEM>>>(x_h, x_l, w_h + 0 * WSLOT,
                                               nullptr, qry, nullptr, nullptr);
    ln_split<<<M_SML, blk>>>(qry, qn_h, qn_l, ln_q_w, ln_q_b);
    // in-proj q/k/v
    gemm_f16x2<1><<<gridSml, blk, GEMM_SMEM>>>(qn_h, qn_l, w_h + 5 * WSLOT,
                                               in_b, qh, nullptr, nullptr);
    gemm_f16x2<1><<<gridBig, blk, GEMM_SMEM>>>(kn_h, kn_l, w_h + 6 * WSLOT,
                                               in_b + E_DIM, kh, nullptr, nullptr);
    gemm_f16x2<1><<<gridBig, blk, GEMM_SMEM>>>(vn_h, vn_l, w_h + 7 * WSLOT,
                                               in_b + 2 * E_DIM, vh, nullptr, nullptr);
    // attention
    attn_split<<<M_SML, blk>>>(qh, kh, vh, at_h, at_l);
    // out-proj -> d_out
    gemm_f16x2<1><<<gridSml, blk, GEMM_SMEM>>>(at_h, at_l, w_h + 8 * WSLOT,
                                               out_b, out, nullptr, nullptr);
}